// round 13
// baseline (speedup 1.0000x reference)
#include <cuda_runtime.h>
#include <cuda_bf16.h>
#include <cstdint>
#include <math.h>

// ---------------------------------------------------------------------------
// Scratch (no allocs allowed -> __device__ globals)
// ---------------------------------------------------------------------------
__device__ float g_bufA[4096 * 1024];
__device__ float g_bufB[4096 * 1024];
__device__ __nv_bfloat16 g_actx2[4096 * 3072];   // ext activations [M, 3*1024]
__device__ __nv_bfloat16 g_w0x[1024 * 3072];     // W^T extended [N_pad, 3*K_pad]
__device__ __nv_bfloat16 g_w1e[1024 * 6144];     // W1 ext (act-style) [1024, 3*2048]
__device__ __nv_bfloat16 g_w2x[1024 * 6144];     // W2^T ext [1024, 3*2048]
__device__ __nv_bfloat16 g_w3x[1024 * 3072];
__device__ __nv_bfloat16 g_wcx[1024 * 3072];     // Wc^T ext [1024, 3*1024]
__device__ float g_wcPart[4 * 1024 * 1024];      // split-K partials for Wc
__device__ float g_bias3[1024];
__device__ float g_biasC[1024];

// ---------------------------------------------------------------------------
// PTX helpers (baseline sm_80+ features only: cp.async, ldmatrix, mma.sync)
// ---------------------------------------------------------------------------
__device__ __forceinline__ uint32_t smem_u32(const void* p) {
    uint32_t a;
    asm("{ .reg .u64 t; cvta.to.shared.u64 t, %1; cvt.u32.u64 %0, t; }"
        : "=r"(a) : "l"(p));
    return a;
}

#define CP_ASYNC16(dst_u32, src_ptr)                                          \
    asm volatile("cp.async.cg.shared.global [%0], [%1], 16;"                  \
                 :: "r"(dst_u32), "l"(src_ptr))
#define CP_COMMIT() asm volatile("cp.async.commit_group;" ::: "memory")
#define CP_WAIT(n)  asm volatile("cp.async.wait_group %0;" :: "n"(n) : "memory")

#define LDSM_X4(r0, r1, r2, r3, addr)                                         \
    asm volatile("ldmatrix.sync.aligned.m8n8.x4.shared.b16 {%0,%1,%2,%3}, [%4];" \
                 : "=r"(r0), "=r"(r1), "=r"(r2), "=r"(r3) : "r"(addr))

#define MMA_16816(d, a, b)                                                    \
    asm volatile(                                                             \
        "mma.sync.aligned.m16n8k16.row.col.f32.bf16.bf16.f32 "                \
        "{%0,%1,%2,%3}, {%4,%5,%6,%7}, {%8,%9}, {%0,%1,%2,%3};"               \
        : "+f"((d)[0]), "+f"((d)[1]), "+f"((d)[2]), "+f"((d)[3])              \
        : "r"((a)[0]), "r"((a)[1]), "r"((a)[2]), "r"((a)[3]),                 \
          "r"((b)[0]), "r"((b)[1]))

// ---------------------------------------------------------------------------
// Circuit schedule table (host-computed, structure is weight-independent).
// m/r = per-gate pair mask + side-selector row. finv = columns of P^{-1}.
// ---------------------------------------------------------------------------
struct CircTab {
    unsigned short m[30];
    unsigned short r[30];
    unsigned short finv[10];
};

// ---------------------------------------------------------------------------
// Conversion kernels: fp32 -> extended bf16 (hi|lo|hi for A, hi|hi|lo for B)
// ---------------------------------------------------------------------------
__global__ __launch_bounds__(256) void convert_act(
    const float* __restrict__ in, __nv_bfloat16* __restrict__ out,
    int K_in, int K_pad)
{
    int idx = blockIdx.x * 256 + threadIdx.x;     // over rows * K_pad
    int r = idx / K_pad;
    int k = idx - r * K_pad;
    float x = (k < K_in) ? in[(size_t)r * K_in + k] : 0.0f;
    __nv_bfloat16 hi = __float2bfloat16(x);
    __nv_bfloat16 lo = __float2bfloat16(x - __bfloat162float(hi));
    size_t base = (size_t)r * 3 * K_pad;
    out[base + k] = hi;                 // hi block
    out[base + K_pad + k] = lo;         // lo block  (pairs with B's hi)
    out[base + 2 * K_pad + k] = hi;     // hi block  (pairs with B's lo)
}

// W [K_in, N_in] row-major  ->  out [N_pad, 3*K_pad] (transposed, hi|hi|lo)
__global__ __launch_bounds__(256) void convert_weight(
    const float* __restrict__ W, __nv_bfloat16* __restrict__ out,
    int K_in, int N_in, int K_pad, int N_pad)
{
    __shared__ float t[32][33];
    int k0 = blockIdx.x * 32, n0 = blockIdx.y * 32;
    int tx = threadIdx.x & 31, ty = threadIdx.x >> 5;   // ty 0..7
    #pragma unroll
    for (int i = 0; i < 32; i += 8) {
        int k = k0 + ty + i, n = n0 + tx;
        t[ty + i][tx] = (k < K_in && n < N_in) ? W[(size_t)k * N_in + n] : 0.0f;
    }
    __syncthreads();
    size_t K3 = 3 * (size_t)K_pad;
    #pragma unroll
    for (int i = 0; i < 32; i += 8) {
        int n = n0 + ty + i, k = k0 + tx;
        if (n < N_pad && k < K_pad) {
            float x = t[tx][ty + i];
            __nv_bfloat16 hi = __float2bfloat16(x);
            __nv_bfloat16 lo = __float2bfloat16(x - __bfloat162float(hi));
            __nv_bfloat16* row = out + (size_t)n * K3;
            row[k] = hi;
            row[K_pad + k] = hi;
            row[2 * K_pad + k] = lo;
        }
    }
}

__global__ void pad_bias(const float* __restrict__ b, float* __restrict__ out,
                         int n_in)
{
    int i = blockIdx.x * 256 + threadIdx.x;
    out[i] = (i < n_in) ? b[i] : 0.0f;
}

// bc[j] = sum_k b1[k] * W2[k][j] + b2[j]     (W2: [2048, 1024])
__global__ __launch_bounds__(256) void bias_compose(
    const float* __restrict__ b1, const float* __restrict__ W2,
    const float* __restrict__ b2, float* __restrict__ out)
{
    int j = blockIdx.x * 256 + threadIdx.x;   // 0..1023
    float s0 = 0.0f, s1 = 0.0f, s2 = 0.0f, s3 = 0.0f;
    #pragma unroll 4
    for (int k = 0; k < 2048; k += 4) {
        s0 += b1[k + 0] * W2[(size_t)(k + 0) * 1024 + j];
        s1 += b1[k + 1] * W2[(size_t)(k + 1) * 1024 + j];
        s2 += b1[k + 2] * W2[(size_t)(k + 2) * 1024 + j];
        s3 += b1[k + 3] * W2[(size_t)(k + 3) * 1024 + j];
    }
    out[j] = (s0 + s1) + (s2 + s3) + b2[j];
}

// Sum the 4 split-K partial planes (deterministic, no atomics)
__global__ __launch_bounds__(256) void reduce4(
    const float* __restrict__ p, float* __restrict__ out)
{
    int i = blockIdx.x * 256 + threadIdx.x;   // 0..1M-1
    const int PL = 1024 * 1024;
    out[i] = (p[i] + p[i + PL]) + (p[i + 2 * PL] + p[i + 3 * PL]);
}

// ---------------------------------------------------------------------------
// mma.sync GEMM (unchanged from R12). See R12 comments.
// ---------------------------------------------------------------------------
#define TILE_BYTES 16384          // 128 rows * 128 B
#define STAGE_BYTES (2 * TILE_BYTES)

__global__ __launch_bounds__(128, 2) void gemm_mma(
    int Kx, int lda, int ldc, int mode,
    const __nv_bfloat16* __restrict__ A, const __nv_bfloat16* __restrict__ B,
    const float* __restrict__ bias, float* __restrict__ C)
{
    extern __shared__ char smem[];
    uint32_t sb = smem_u32(smem);

    const int tid = threadIdx.x;
    const int wid = tid >> 5, lane = tid & 31;
    const int bm = blockIdx.y * 128, bn = blockIdx.x * 128;
    const int koff = blockIdx.z * Kx;
    const int wm = (wid & 1) * 64;
    const int wn = (wid >> 1) * 64;

    float d[4][8][4];
    #pragma unroll
    for (int mt = 0; mt < 4; mt++)
        #pragma unroll
        for (int nt = 0; nt < 8; nt++)
            #pragma unroll
            for (int e = 0; e < 4; e++)
                d[mt][nt][e] = 0.0f;

    const int nch = Kx >> 6;

    auto load_chunk = [&](int ch, int buf) {
        const int kc = koff + (ch << 6);
        uint32_t sA = sb + buf * STAGE_BYTES;
        uint32_t sB = sA + TILE_BYTES;
        #pragma unroll
        for (int it = 0; it < 8; it++) {
            int f = tid + it * 128;
            int r = f >> 3, c16 = f & 7;
            uint32_t off = (uint32_t)(r * 128 + c16 * 16);
            off ^= (off >> 3) & 0x70;
            const __nv_bfloat16* srcA = A + (size_t)(bm + r) * lda + kc + c16 * 8;
            const __nv_bfloat16* srcB = B + (size_t)(bn + r) * lda + kc + c16 * 8;
            CP_ASYNC16(sA + off, srcA);
            CP_ASYNC16(sB + off, srcB);
        }
    };

    load_chunk(0, 0);
    CP_COMMIT();

    for (int ch = 0; ch < nch; ch++) {
        const int cur = ch & 1;
        if (ch + 1 < nch) {
            load_chunk(ch + 1, cur ^ 1);
            CP_COMMIT();
            CP_WAIT(1);
        } else {
            CP_WAIT(0);
        }
        __syncthreads();

        uint32_t sA = sb + cur * STAGE_BYTES;
        uint32_t sB = sA + TILE_BYTES;

        #pragma unroll
        for (int s = 0; s < 4; s++) {
            uint32_t a[4][4];
            uint32_t b[8][2];
            #pragma unroll
            for (int mt = 0; mt < 4; mt++) {
                int row = wm + mt * 16 + (lane & 15);
                int colb = s * 32 + ((lane >> 4) & 1) * 16;
                uint32_t off = (uint32_t)(row * 128 + colb);
                off ^= (off >> 3) & 0x70;
                LDSM_X4(a[mt][0], a[mt][1], a[mt][2], a[mt][3], sA + off);
            }
            #pragma unroll
            for (int nt2 = 0; nt2 < 4; nt2++) {
                int row = wn + nt2 * 16 + ((lane >> 4) & 1) * 8 + (lane & 7);
                int colb = s * 32 + ((lane >> 3) & 1) * 16;
                uint32_t off = (uint32_t)(row * 128 + colb);
                off ^= (off >> 3) & 0x70;
                uint32_t r0, r1, r2, r3;
                LDSM_X4(r0, r1, r2, r3, sB + off);
                b[nt2 * 2 + 0][0] = r0; b[nt2 * 2 + 0][1] = r1;
                b[nt2 * 2 + 1][0] = r2; b[nt2 * 2 + 1][1] = r3;
            }
            #pragma unroll
            for (int mt = 0; mt < 4; mt++)
                #pragma unroll
                for (int nt = 0; nt < 8; nt++)
                    MMA_16816(d[mt][nt], a[mt], b[nt]);
        }
        __syncthreads();
    }

    const int er = lane >> 2;
    const int ec = (lane & 3) * 2;
    float* Co = C;
    if (mode == 2) {
        size_t plane = (size_t)(gridDim.x * 128) * (size_t)(gridDim.y * 128);
        Co += (size_t)blockIdx.z * plane;
    }
    #pragma unroll
    for (int nt = 0; nt < 8; nt++) {
        int col = bn + wn + nt * 8 + ec;
        float b0 = 0.0f, b1 = 0.0f;
        if (mode == 0) { b0 = bias[col]; b1 = bias[col + 1]; }
        #pragma unroll
        for (int mt = 0; mt < 4; mt++) {
            int row = bm + wm + mt * 16 + er;
            float2 v0 = make_float2(d[mt][nt][0] + b0, d[mt][nt][1] + b1);
            float2 v1 = make_float2(d[mt][nt][2] + b0, d[mt][nt][3] + b1);
            *reinterpret_cast<float2*>(Co + (size_t)row * ldc + col) = v0;
            *reinterpret_cast<float2*>(Co + (size_t)(row + 8) * ldc + col) = v1;
        }
    }
}

// ---------------------------------------------------------------------------
// Quantum circuit kernel v2: register-resident amplitudes.
// Thread t owns amplitudes i = 4t..4t+3 (re[4], im[4] in registers).
// Gate mask m: m<4 in-thread; m<128 same-warp -> __shfl_xor (no syncs);
// m>=128 cross-warp -> smem stage (2 syncs). Side parity e from <r[g], i>.
// Output applies P^{-1} (finv columns) and writes ext bf16 hi|lo|hi.
// ---------------------------------------------------------------------------
__global__ __launch_bounds__(256) void circuit_kernel(
    const float* __restrict__ x,          // [4096, 1024] fp32
    const float* __restrict__ w,          // [3, 10, 3]
    CircTab tab,
    __nv_bfloat16* __restrict__ out)      // [4096, 3*1024] ext bf16
{
    __shared__ float Ug[30][4];
    __shared__ float red[8];
    __shared__ float stR[1024];
    __shared__ float stI[1024];

    const int row = blockIdx.x;
    const int tid = threadIdx.x;

    if (tid < 30) {
        float phi = w[tid * 3 + 0];
        float th  = w[tid * 3 + 1];
        float om  = w[tid * 3 + 2];
        float s, c;   sincosf(0.5f * th, &s, &c);
        float sa, ca; sincosf(0.5f * (phi + om), &sa, &ca);
        float sb, cb; sincosf(0.5f * (phi - om), &sb, &cb);
        Ug[tid][0] = ca * c;
        Ug[tid][1] = sa * c;
        Ug[tid][2] = cb * s;
        Ug[tid][3] = sb * s;
    }

    // Load own 4 amplitudes, L2-normalize the row
    float4 v4 = *reinterpret_cast<const float4*>(x + (size_t)row * 1024 + tid * 4);
    float re[4] = {v4.x, v4.y, v4.z, v4.w};
    float im[4] = {0.0f, 0.0f, 0.0f, 0.0f};
    float ss = re[0]*re[0] + re[1]*re[1] + re[2]*re[2] + re[3]*re[3];
    #pragma unroll
    for (int o = 16; o > 0; o >>= 1)
        ss += __shfl_xor_sync(0xFFFFFFFFu, ss, o);
    if ((tid & 31) == 0) red[tid >> 5] = ss;
    __syncthreads();                      // also publishes Ug
    float tot = 0.0f;
    #pragma unroll
    for (int j = 0; j < 8; j++) tot += red[j];
    float inv = rsqrtf(tot);
    #pragma unroll
    for (int j = 0; j < 4; j++) re[j] *= inv;

    for (int g = 0; g < 30; g++) {
        const unsigned m  = tab.m[g];
        const unsigned rr = tab.r[g];
        const float Am = Ug[g][0], Bm = Ug[g][1];
        const float Cm = Ug[g][2], Dm = Ug[g][3];
        float pr[4], pi[4];

        if (m >= 128) {
            // cross-warp: stage in smem
            __syncthreads();
            #pragma unroll
            for (int j = 0; j < 4; j++) {
                stR[tid * 4 + j] = re[j];
                stI[tid * 4 + j] = im[j];
            }
            __syncthreads();
            #pragma unroll
            for (int j = 0; j < 4; j++) {
                unsigned q = ((unsigned)tid * 4 + j) ^ m;
                pr[j] = stR[q];
                pi[j] = stI[q];
            }
        } else if (m >= 4) {
            const unsigned lx = m >> 2;       // lane xor (1..31)
            switch (m & 3) {
            case 0:
                #pragma unroll
                for (int j = 0; j < 4; j++) {
                    pr[j] = __shfl_xor_sync(0xFFFFFFFFu, re[j], lx);
                    pi[j] = __shfl_xor_sync(0xFFFFFFFFu, im[j], lx);
                }
                break;
            case 1:
                #pragma unroll
                for (int j = 0; j < 4; j++) {
                    pr[j] = __shfl_xor_sync(0xFFFFFFFFu, re[j ^ 1], lx);
                    pi[j] = __shfl_xor_sync(0xFFFFFFFFu, im[j ^ 1], lx);
                }
                break;
            case 2:
                #pragma unroll
                for (int j = 0; j < 4; j++) {
                    pr[j] = __shfl_xor_sync(0xFFFFFFFFu, re[j ^ 2], lx);
                    pi[j] = __shfl_xor_sync(0xFFFFFFFFu, im[j ^ 2], lx);
                }
                break;
            default:
                #pragma unroll
                for (int j = 0; j < 4; j++) {
                    pr[j] = __shfl_xor_sync(0xFFFFFFFFu, re[j ^ 3], lx);
                    pi[j] = __shfl_xor_sync(0xFFFFFFFFu, im[j ^ 3], lx);
                }
                break;
            }
        } else {
            // in-thread partner
            switch (m) {
            case 1:
                #pragma unroll
                for (int j = 0; j < 4; j++) { pr[j] = re[j ^ 1]; pi[j] = im[j ^ 1]; }
                break;
            case 2:
                #pragma unroll
                for (int j = 0; j < 4; j++) { pr[j] = re[j ^ 2]; pi[j] = im[j ^ 2]; }
                break;
            default:
                #pragma unroll
                for (int j = 0; j < 4; j++) { pr[j] = re[j ^ 3]; pi[j] = im[j ^ 3]; }
                break;
            }
        }

        #pragma unroll
        for (int j = 0; j < 4; j++) {
            unsigned i = (unsigned)tid * 4 + j;
            float e = (__popc(i & rr) & 1) ? 1.0f : -1.0f;
            float eB = e * Bm, eC = e * Cm;
            float r0 = re[j], i0 = im[j];
            re[j] = Am * r0 - eB * i0 + eC * pr[j] + Dm * pi[j];
            im[j] = Am * i0 + eB * r0 + eC * pi[j] - Dm * pr[j];
        }
    }

    // probs: physical index i holds logical b = P^{-1}(i); scatter ext bf16
    size_t base = (size_t)row * 3072;
    #pragma unroll
    for (int j = 0; j < 4; j++) {
        unsigned i = (unsigned)tid * 4 + j;
        unsigned b = 0;
        #pragma unroll
        for (int k2 = 0; k2 < 10; k2++)
            if ((i >> k2) & 1) b ^= tab.finv[k2];
        float p = re[j] * re[j] + im[j] * im[j];
        __nv_bfloat16 hi = __float2bfloat16(p);
        __nv_bfloat16 lo = __float2bfloat16(p - __bfloat162float(hi));
        out[base + b] = hi;
        out[base + 1024 + b] = lo;
        out[base + 2048 + b] = hi;
    }
}

// ---------------------------------------------------------------------------
// Final: y = |x| ; y /= rowsum(y)   x: [4096, 1024-strided], out: [4096, 1000]
// ---------------------------------------------------------------------------
__global__ __launch_bounds__(256) void abs_norm_kernel(
    const float* __restrict__ x, float* __restrict__ out)
{
    __shared__ float red[8];
    const int row = blockIdx.x;
    const int tid = threadIdx.x;

    float v[4];
    float ss = 0.0f;
    #pragma unroll
    for (int j = 0; j < 4; j++) {
        int i = tid + j * 256;
        v[j] = (i < 1000) ? fabsf(x[(size_t)row * 1024 + i]) : 0.0f;
        ss += v[j];
    }
    #pragma unroll
    for (int o = 16; o > 0; o >>= 1)
        ss += __shfl_xor_sync(0xFFFFFFFFu, ss, o);
    if ((tid & 31) == 0) red[tid >> 5] = ss;
    __syncthreads();
    float tot = 0.0f;
    #pragma unroll
    for (int j = 0; j < 8; j++) tot += red[j];
    float inv = 1.0f / tot;
    #pragma unroll
    for (int j = 0; j < 4; j++) {
        int i = tid + j * 256;
        if (i < 1000)
            out[(size_t)row * 1000 + i] = v[j] * inv;
    }
}

// ---------------------------------------------------------------------------
// Host: compute circuit schedule (structure-only, weight-independent).
// pc[j] = column j of P; pr[j] = row j of P^{-1}; finv[k] = column k of P^{-1}.
// ---------------------------------------------------------------------------
static CircTab make_circ_tab()
{
    unsigned pc[10], pr[10];
    for (int j = 0; j < 10; j++) { pc[j] = 1u << j; pr[j] = 1u << j; }
    CircTab t;
    for (int l = 0; l < 3; l++) {
        for (int q = 0; q < 10; q++) {
            int g = l * 10 + q, b = 9 - q;          // wire q <-> bit 9-q
            t.m[g] = (unsigned short)pc[b];
            t.r[g] = (unsigned short)pr[b];
        }
        int rr = l % 9 + 1;
        for (int q = 0; q < 10; q++) {
            int c = 9 - q;                           // control bit
            int tt = 9 - ((q + rr) % 10);            // target bit
            pc[c] ^= pc[tt];                         // P' = P * C (column op)
            pr[tt] ^= pr[c];                         // P'^-1 = C * P^-1 (row op)
        }
    }
    for (int k = 0; k < 10; k++) {
        unsigned col = 0;
        for (int j = 0; j < 10; j++)
            col |= ((pr[j] >> k) & 1u) << j;
        t.finv[k] = (unsigned short)col;
    }
    return t;
}

// ---------------------------------------------------------------------------
// Launch
// ---------------------------------------------------------------------------
extern "C" void kernel_launch(void* const* d_in, const int* in_sizes, int n_in,
                              void* d_out, int out_size)
{
    const float* inputs = (const float*)d_in[0];
    const float* wEnc   = (const float*)d_in[1];
    const float* wDec   = (const float*)d_in[2];
    const float* W0     = (const float*)d_in[3];
    const float* b0     = (const float*)d_in[4];
    const float* W1     = (const float*)d_in[5];
    const float* b1     = (const float*)d_in[6];
    const float* W2     = (const float*)d_in[7];
    const float* b2     = (const float*)d_in[8];
    const float* W3     = (const float*)d_in[9];
    const float* b3     = (const float*)d_in[10];
    float* outp = (float*)d_out;

    float *bufA = nullptr, *bufB = nullptr, *bias3 = nullptr, *biasC = nullptr,
          *wcPart = nullptr;
    __nv_bfloat16 *actx2 = nullptr, *w0x = nullptr, *w1e = nullptr,
                  *w2x = nullptr, *w3x = nullptr, *wcx = nullptr;
    cudaGetSymbolAddress((void**)&bufA, g_bufA);
    cudaGetSymbolAddress((void**)&bufB, g_bufB);
    cudaGetSymbolAddress((void**)&bias3, g_bias3);
    cudaGetSymbolAddress((void**)&biasC, g_biasC);
    cudaGetSymbolAddress((void**)&wcPart, g_wcPart);
    cudaGetSymbolAddress((void**)&actx2, g_actx2);
    cudaGetSymbolAddress((void**)&w0x, g_w0x);
    cudaGetSymbolAddress((void**)&w1e, g_w1e);
    cudaGetSymbolAddress((void**)&w2x, g_w2x);
    cudaGetSymbolAddress((void**)&w3x, g_w3x);
    cudaGetSymbolAddress((void**)&wcx, g_wcx);

    const CircTab tab = make_circ_tab();

    dim3 blk(256);
    dim3 blkg(128);
    const int GSMEM = 2 * STAGE_BYTES;   // 65536 B dynamic smem (double buffer)
    cudaFuncSetAttribute(gemm_mma,
                         cudaFuncAttributeMaxDynamicSharedMemorySize, GSMEM);

    // ---- Weight prep (per-launch, deterministic) ----
    convert_weight<<<dim3(32, 32), blk>>>(W0, w0x, 1000, 1024, 1024, 1024);
    convert_weight<<<dim3(64, 32), blk>>>(W2, w2x, 2048, 1024, 2048, 1024);
    convert_weight<<<dim3(32, 32), blk>>>(W3, w3x, 1024, 1000, 1024, 1024);
    pad_bias<<<4, blk>>>(b3, bias3, 1000);

    // ---- Fuse W1@W2 -> Wc (split-K=4, deterministic partials + reduce) ----
    convert_act<<<1024 * 2048 / 256, blk>>>(W1, w1e, 2048, 2048);
    gemm_mma<<<dim3(8, 8, 4), blkg, GSMEM>>>(1536, 6144, 1024, 2,
                                             w1e, w2x, bias3, wcPart);
    reduce4<<<4096, blk>>>(wcPart, bufB);               // Wc fp32 [1024,1024]
    bias_compose<<<4, blk>>>(b1, W2, b2, biasC);        // bc = b1@W2 + b2
    convert_weight<<<dim3(32, 32), blk>>>(bufB, wcx, 1024, 1024, 1024, 1024);

    // ---- Main path ----
    // x = inputs @ W0 + b0                       [4096,1024] fp32
    convert_act<<<4096 * 1024 / 256, blk>>>(inputs, actx2, 1000, 1024);
    gemm_mma<<<dim3(8, 32), blkg, GSMEM>>>(3072, 3072, 1024, 0,
                                           actx2, w0x, b0, bufA);
    // x = circuit(x, wEnc) -> ext bf16
    circuit_kernel<<<4096, blk>>>(bufA, wEnc, tab, actx2);
    // x = x @ Wc + bc                            [4096,1024] fp32
    gemm_mma<<<dim3(8, 32), blkg, GSMEM>>>(3072, 3072, 1024, 0,
                                           actx2, wcx, biasC, bufA);
    // x = circuit(x, wDec) -> ext bf16
    circuit_kernel<<<4096, blk>>>(bufA, wDec, tab, actx2);
    // x = x @ W3 + b3                            [4096,1024-padded] fp32
    gemm_mma<<<dim3(8, 32), blkg, GSMEM>>>(3072, 3072, 1024, 0,
                                           actx2, w3x, bias3, bufB);
    // out = |x| / rowsum(|x|)
    abs_norm_kernel<<<4096, blk>>>(bufB, outp);
}

// round 14
// speedup vs baseline: 1.2302x; 1.2302x over previous
#include <cuda_runtime.h>
#include <cuda_bf16.h>
#include <cstdint>
#include <math.h>

// ---------------------------------------------------------------------------
// Scratch (no allocs allowed -> __device__ globals)
// ---------------------------------------------------------------------------
__device__ float g_bufA[4096 * 1024];
__device__ float g_bufB[4096 * 1024];
__device__ __nv_bfloat16 g_actx2[4096 * 3072];   // ext activations [M, 3*1024]
__device__ __nv_bfloat16 g_w0x[1024 * 3072];     // W^T extended [N_pad, 3*K_pad]
__device__ __nv_bfloat16 g_w1e[1024 * 6144];     // W1 ext (act-style) [1024, 3*2048]
__device__ __nv_bfloat16 g_w2x[1024 * 6144];     // W2^T ext [1024, 3*2048]
__device__ __nv_bfloat16 g_w3x[1024 * 3072];
__device__ __nv_bfloat16 g_wcx[1024 * 3072];     // Wc^T ext [1024, 3*1024]
__device__ float g_wcPart[4 * 1024 * 1024];      // split-K partials for Wc
__device__ float g_bias3[1024];
__device__ float g_biasC[1024];

// ---------------------------------------------------------------------------
// PTX helpers (baseline sm_80+ features only: cp.async, ldmatrix, mma.sync)
// ---------------------------------------------------------------------------
__device__ __forceinline__ uint32_t smem_u32(const void* p) {
    uint32_t a;
    asm("{ .reg .u64 t; cvta.to.shared.u64 t, %1; cvt.u32.u64 %0, t; }"
        : "=r"(a) : "l"(p));
    return a;
}

#define CP_ASYNC16(dst_u32, src_ptr)                                          \
    asm volatile("cp.async.cg.shared.global [%0], [%1], 16;"                  \
                 :: "r"(dst_u32), "l"(src_ptr))
#define CP_COMMIT() asm volatile("cp.async.commit_group;" ::: "memory")
#define CP_WAIT(n)  asm volatile("cp.async.wait_group %0;" :: "n"(n) : "memory")

#define LDSM_X4(r0, r1, r2, r3, addr)                                         \
    asm volatile("ldmatrix.sync.aligned.m8n8.x4.shared.b16 {%0,%1,%2,%3}, [%4];" \
                 : "=r"(r0), "=r"(r1), "=r"(r2), "=r"(r3) : "r"(addr))

#define MMA_16816(d, a, b)                                                    \
    asm volatile(                                                             \
        "mma.sync.aligned.m16n8k16.row.col.f32.bf16.bf16.f32 "                \
        "{%0,%1,%2,%3}, {%4,%5,%6,%7}, {%8,%9}, {%0,%1,%2,%3};"               \
        : "+f"((d)[0]), "+f"((d)[1]), "+f"((d)[2]), "+f"((d)[3])              \
        : "r"((a)[0]), "r"((a)[1]), "r"((a)[2]), "r"((a)[3]),                 \
          "r"((b)[0]), "r"((b)[1]))

// ---------------------------------------------------------------------------
// Circuit schedule table (host-computed, structure is weight-independent).
// m/r = per-gate pair mask + side-selector row. fcol = columns of P.
// ---------------------------------------------------------------------------
struct CircTab {
    unsigned short m[30];
    unsigned short r[30];
    unsigned short fcol[10];
};

// ---------------------------------------------------------------------------
// Conversion kernels: fp32 -> extended bf16 (hi|lo|hi for A, hi|hi|lo for B)
// ---------------------------------------------------------------------------
__global__ __launch_bounds__(256) void convert_act(
    const float* __restrict__ in, __nv_bfloat16* __restrict__ out,
    int K_in, int K_pad)
{
    int idx = blockIdx.x * 256 + threadIdx.x;     // over rows * K_pad
    int r = idx / K_pad;
    int k = idx - r * K_pad;
    float x = (k < K_in) ? in[(size_t)r * K_in + k] : 0.0f;
    __nv_bfloat16 hi = __float2bfloat16(x);
    __nv_bfloat16 lo = __float2bfloat16(x - __bfloat162float(hi));
    size_t base = (size_t)r * 3 * K_pad;
    out[base + k] = hi;                 // hi block
    out[base + K_pad + k] = lo;         // lo block  (pairs with B's hi)
    out[base + 2 * K_pad + k] = hi;     // hi block  (pairs with B's lo)
}

// W [K_in, N_in] row-major  ->  out [N_pad, 3*K_pad] (transposed, hi|hi|lo)
__global__ __launch_bounds__(256) void convert_weight(
    const float* __restrict__ W, __nv_bfloat16* __restrict__ out,
    int K_in, int N_in, int K_pad, int N_pad)
{
    __shared__ float t[32][33];
    int k0 = blockIdx.x * 32, n0 = blockIdx.y * 32;
    int tx = threadIdx.x & 31, ty = threadIdx.x >> 5;   // ty 0..7
    #pragma unroll
    for (int i = 0; i < 32; i += 8) {
        int k = k0 + ty + i, n = n0 + tx;
        t[ty + i][tx] = (k < K_in && n < N_in) ? W[(size_t)k * N_in + n] : 0.0f;
    }
    __syncthreads();
    size_t K3 = 3 * (size_t)K_pad;
    #pragma unroll
    for (int i = 0; i < 32; i += 8) {
        int n = n0 + ty + i, k = k0 + tx;
        if (n < N_pad && k < K_pad) {
            float x = t[tx][ty + i];
            __nv_bfloat16 hi = __float2bfloat16(x);
            __nv_bfloat16 lo = __float2bfloat16(x - __bfloat162float(hi));
            __nv_bfloat16* row = out + (size_t)n * K3;
            row[k] = hi;
            row[K_pad + k] = hi;
            row[2 * K_pad + k] = lo;
        }
    }
}

// Fused: sum 4 split-K partial planes [1024,1024] + transpose + ext bf16.
// out[n, 3*1024] = hi|hi|lo of Wc[k,n].
__global__ __launch_bounds__(256) void reduce_convert_weight(
    const float* __restrict__ p, __nv_bfloat16* __restrict__ out)
{
    __shared__ float t[32][33];
    const int PL = 1024 * 1024;
    int k0 = blockIdx.x * 32, n0 = blockIdx.y * 32;
    int tx = threadIdx.x & 31, ty = threadIdx.x >> 5;   // ty 0..7
    #pragma unroll
    for (int i = 0; i < 32; i += 8) {
        size_t idx = (size_t)(k0 + ty + i) * 1024 + n0 + tx;
        t[ty + i][tx] = (p[idx] + p[idx + PL]) + (p[idx + 2 * PL] + p[idx + 3 * PL]);
    }
    __syncthreads();
    #pragma unroll
    for (int i = 0; i < 32; i += 8) {
        int n = n0 + ty + i, k = k0 + tx;
        float x = t[tx][ty + i];
        __nv_bfloat16 hi = __float2bfloat16(x);
        __nv_bfloat16 lo = __float2bfloat16(x - __bfloat162float(hi));
        __nv_bfloat16* row = out + (size_t)n * 3072;
        row[k] = hi;
        row[1024 + k] = hi;
        row[2048 + k] = lo;
    }
}

__global__ void pad_bias(const float* __restrict__ b, float* __restrict__ out,
                         int n_in)
{
    int i = blockIdx.x * 256 + threadIdx.x;
    out[i] = (i < n_in) ? b[i] : 0.0f;
}

// bc[j] = sum_k b1[k] * W2[k][j] + b2[j]     (W2: [2048, 1024])
__global__ __launch_bounds__(256) void bias_compose(
    const float* __restrict__ b1, const float* __restrict__ W2,
    const float* __restrict__ b2, float* __restrict__ out)
{
    int j = blockIdx.x * 256 + threadIdx.x;   // 0..1023
    float s0 = 0.0f, s1 = 0.0f, s2 = 0.0f, s3 = 0.0f;
    #pragma unroll 4
    for (int k = 0; k < 2048; k += 4) {
        s0 += b1[k + 0] * W2[(size_t)(k + 0) * 1024 + j];
        s1 += b1[k + 1] * W2[(size_t)(k + 1) * 1024 + j];
        s2 += b1[k + 2] * W2[(size_t)(k + 2) * 1024 + j];
        s3 += b1[k + 3] * W2[(size_t)(k + 3) * 1024 + j];
    }
    out[j] = (s0 + s1) + (s2 + s3) + b2[j];
}

// ---------------------------------------------------------------------------
// mma.sync GEMM: C[M,N] = A'[M,*] @ B'[N,*]^T (+ bias)   (bf16 in)
// CTA tile 128x128, BK=64 (128B rows, XOR-swizzled), cp.async 3-stage.
// 4 warps (128 threads), warp tile 64x64. grid = (N/128, M/128, Ksplit).
// mode 0: write fp32 C (+bias). mode 2: write fp32 partial plane z (no bias).
// ---------------------------------------------------------------------------
#define TILE_BYTES 16384          // 128 rows * 128 B
#define STAGE_BYTES (2 * TILE_BYTES)
#define NSTAGE 3

__global__ __launch_bounds__(128, 2) void gemm_mma(
    int Kx, int lda, int ldc, int mode,
    const __nv_bfloat16* __restrict__ A, const __nv_bfloat16* __restrict__ B,
    const float* __restrict__ bias, float* __restrict__ C)
{
    extern __shared__ char smem[];
    uint32_t sb = smem_u32(smem);

    const int tid = threadIdx.x;
    const int wid = tid >> 5, lane = tid & 31;
    const int bm = blockIdx.y * 128, bn = blockIdx.x * 128;
    const int koff = blockIdx.z * Kx;
    const int wm = (wid & 1) * 64;
    const int wn = (wid >> 1) * 64;

    float d[4][8][4];
    #pragma unroll
    for (int mt = 0; mt < 4; mt++)
        #pragma unroll
        for (int nt = 0; nt < 8; nt++)
            #pragma unroll
            for (int e = 0; e < 4; e++)
                d[mt][nt][e] = 0.0f;

    const int nch = Kx >> 6;

    auto load_chunk = [&](int ch, int buf) {
        const int kc = koff + (ch << 6);
        uint32_t sA = sb + buf * STAGE_BYTES;
        uint32_t sB = sA + TILE_BYTES;
        #pragma unroll
        for (int it = 0; it < 8; it++) {
            int f = tid + it * 128;
            int r = f >> 3, c16 = f & 7;
            uint32_t off = (uint32_t)(r * 128 + c16 * 16);
            off ^= (off >> 3) & 0x70;
            const __nv_bfloat16* srcA = A + (size_t)(bm + r) * lda + kc + c16 * 8;
            const __nv_bfloat16* srcB = B + (size_t)(bn + r) * lda + kc + c16 * 8;
            CP_ASYNC16(sA + off, srcA);
            CP_ASYNC16(sB + off, srcB);
        }
    };

    load_chunk(0, 0);
    CP_COMMIT();
    if (nch > 1) {
        load_chunk(1, 1);
        CP_COMMIT();
    }

    for (int ch = 0; ch < nch; ch++) {
        const int cur = ch % NSTAGE;
        if (ch + 2 < nch) {
            load_chunk(ch + 2, (ch + 2) % NSTAGE);
            CP_COMMIT();
            CP_WAIT(2);
        } else if (ch + 1 < nch) {
            CP_WAIT(1);
        } else {
            CP_WAIT(0);
        }
        __syncthreads();

        uint32_t sA = sb + cur * STAGE_BYTES;
        uint32_t sB = sA + TILE_BYTES;

        #pragma unroll
        for (int s = 0; s < 4; s++) {
            uint32_t a[4][4];
            uint32_t b[8][2];
            #pragma unroll
            for (int mt = 0; mt < 4; mt++) {
                int row = wm + mt * 16 + (lane & 15);
                int colb = s * 32 + ((lane >> 4) & 1) * 16;
                uint32_t off = (uint32_t)(row * 128 + colb);
                off ^= (off >> 3) & 0x70;
                LDSM_X4(a[mt][0], a[mt][1], a[mt][2], a[mt][3], sA + off);
            }
            #pragma unroll
            for (int nt2 = 0; nt2 < 4; nt2++) {
                int row = wn + nt2 * 16 + ((lane >> 4) & 1) * 8 + (lane & 7);
                int colb = s * 32 + ((lane >> 3) & 1) * 16;
                uint32_t off = (uint32_t)(row * 128 + colb);
                off ^= (off >> 3) & 0x70;
                uint32_t r0, r1, r2, r3;
                LDSM_X4(r0, r1, r2, r3, sB + off);
                b[nt2 * 2 + 0][0] = r0; b[nt2 * 2 + 0][1] = r1;
                b[nt2 * 2 + 1][0] = r2; b[nt2 * 2 + 1][1] = r3;
            }
            #pragma unroll
            for (int mt = 0; mt < 4; mt++)
                #pragma unroll
                for (int nt = 0; nt < 8; nt++)
                    MMA_16816(d[mt][nt], a[mt], b[nt]);
        }
        __syncthreads();
    }

    const int er = lane >> 2;
    const int ec = (lane & 3) * 2;
    float* Co = C;
    if (mode == 2) {
        size_t plane = (size_t)(gridDim.x * 128) * (size_t)(gridDim.y * 128);
        Co += (size_t)blockIdx.z * plane;
    }
    #pragma unroll
    for (int nt = 0; nt < 8; nt++) {
        int col = bn + wn + nt * 8 + ec;
        float b0 = 0.0f, b1 = 0.0f;
        if (mode == 0) { b0 = bias[col]; b1 = bias[col + 1]; }
        #pragma unroll
        for (int mt = 0; mt < 4; mt++) {
            int row = bm + wm + mt * 16 + er;
            float2 v0 = make_float2(d[mt][nt][0] + b0, d[mt][nt][1] + b1);
            float2 v1 = make_float2(d[mt][nt][2] + b0, d[mt][nt][3] + b1);
            *reinterpret_cast<float2*>(Co + (size_t)row * ldc + col) = v0;
            *reinterpret_cast<float2*>(Co + (size_t)(row + 8) * ldc + col) = v1;
        }
    }
}

// ---------------------------------------------------------------------------
// Quantum circuit kernel (R12 version): one block per batch row. CNOTs
// tracked as GF(2) linear map (CircTab). 30 pair-rotations, 30 syncs.
// Writes probs as extended bf16 hi|lo|hi for the next GEMM.
// ---------------------------------------------------------------------------
__global__ __launch_bounds__(256) void circuit_kernel(
    const float* __restrict__ x,          // [4096, 1024] fp32
    const float* __restrict__ w,          // [3, 10, 3]
    CircTab tab,
    __nv_bfloat16* __restrict__ out)      // [4096, 3*1024] ext bf16
{
    __shared__ float sre[1024];
    __shared__ float sim[1024];
    __shared__ float Ug[30][4];
    __shared__ float red[8];

    const int row = blockIdx.x;
    const int tid = threadIdx.x;

    if (tid < 30) {
        float phi = w[tid * 3 + 0];
        float th  = w[tid * 3 + 1];
        float om  = w[tid * 3 + 2];
        float s, c;   sincosf(0.5f * th, &s, &c);
        float sa, ca; sincosf(0.5f * (phi + om), &sa, &ca);
        float sb, cb; sincosf(0.5f * (phi - om), &sb, &cb);
        Ug[tid][0] = ca * c;
        Ug[tid][1] = sa * c;
        Ug[tid][2] = cb * s;
        Ug[tid][3] = sb * s;
    }

    float v[4];
    float ss = 0.0f;
    #pragma unroll
    for (int j = 0; j < 4; j++) {
        v[j] = x[(size_t)row * 1024 + tid + j * 256];
        ss += v[j] * v[j];
    }
    #pragma unroll
    for (int o = 16; o > 0; o >>= 1)
        ss += __shfl_xor_sync(0xFFFFFFFFu, ss, o);
    if ((tid & 31) == 0) red[tid >> 5] = ss;
    __syncthreads();
    float tot = 0.0f;
    #pragma unroll
    for (int j = 0; j < 8; j++) tot += red[j];
    float inv = rsqrtf(tot);
    #pragma unroll
    for (int j = 0; j < 4; j++) {
        sre[tid + j * 256] = v[j] * inv;
        sim[tid + j * 256] = 0.0f;
    }
    __syncthreads();

    for (int g = 0; g < 30; g++) {
        const float Am = Ug[g][0], Bm = Ug[g][1];
        const float Cm = Ug[g][2], Dm = Ug[g][3];
        const unsigned m  = tab.m[g];
        const unsigned rr = tab.r[g];
        const unsigned pbm = rr & (0u - rr);       // lowest set bit of rr
        const unsigned lomask = pbm - 1;
        #pragma unroll
        for (int it = 0; it < 2; it++) {
            unsigned p = (unsigned)tid + it * 256; // 0..511
            unsigned lo = p & lomask;
            unsigned y0 = ((p ^ lo) << 1) | lo;    // insert 0 at pivot bit
            unsigned par = __popc(y0 & rr) & 1;
            unsigned i0 = y0 | (par ? pbm : 0u);   // logical bit = 0 side
            unsigned i1 = i0 ^ m;                  // logical bit = 1 partner
            float a0r = sre[i0], a0i = sim[i0];
            float a1r = sre[i1], a1i = sim[i1];
            sre[i0] = Am * a0r + Bm * a0i - Cm * a1r + Dm * a1i;
            sim[i0] = Am * a0i - Bm * a0r - Cm * a1i - Dm * a1r;
            sre[i1] = Cm * a0r + Dm * a0i + Am * a1r - Bm * a1i;
            sim[i1] = Cm * a0i - Dm * a0r + Am * a1i + Bm * a1r;
        }
        __syncthreads();
    }

    // probs at logical index b live at physical P(b) -> ext bf16 (hi|lo|hi)
    size_t base = (size_t)row * 3072;
    #pragma unroll
    for (int j = 0; j < 4; j++) {
        int b = tid + j * 256;
        unsigned phys = 0;
        #pragma unroll
        for (int k2 = 0; k2 < 10; k2++)
            if ((b >> k2) & 1) phys ^= tab.fcol[k2];
        float pre = sre[phys], pim = sim[phys];
        float p = pre * pre + pim * pim;
        __nv_bfloat16 hi = __float2bfloat16(p);
        __nv_bfloat16 lo = __float2bfloat16(p - __bfloat162float(hi));
        out[base + b] = hi;
        out[base + 1024 + b] = lo;
        out[base + 2048 + b] = hi;
    }
}

// ---------------------------------------------------------------------------
// Final: y = |x| ; y /= rowsum(y)   x: [4096, 1024-strided], out: [4096, 1000]
// ---------------------------------------------------------------------------
__global__ __launch_bounds__(256) void abs_norm_kernel(
    const float* __restrict__ x, float* __restrict__ out)
{
    __shared__ float red[8];
    const int row = blockIdx.x;
    const int tid = threadIdx.x;

    float v[4];
    float ss = 0.0f;
    #pragma unroll
    for (int j = 0; j < 4; j++) {
        int i = tid + j * 256;
        v[j] = (i < 1000) ? fabsf(x[(size_t)row * 1024 + i]) : 0.0f;
        ss += v[j];
    }
    #pragma unroll
    for (int o = 16; o > 0; o >>= 1)
        ss += __shfl_xor_sync(0xFFFFFFFFu, ss, o);
    if ((tid & 31) == 0) red[tid >> 5] = ss;
    __syncthreads();
    float tot = 0.0f;
    #pragma unroll
    for (int j = 0; j < 8; j++) tot += red[j];
    float inv = 1.0f / tot;
    #pragma unroll
    for (int j = 0; j < 4; j++) {
        int i = tid + j * 256;
        if (i < 1000)
            out[(size_t)row * 1000 + i] = v[j] * inv;
    }
}

// ---------------------------------------------------------------------------
// Host: compute circuit schedule (structure-only, weight-independent).
// ---------------------------------------------------------------------------
static CircTab make_circ_tab()
{
    unsigned pc[10], pr[10];
    for (int j = 0; j < 10; j++) { pc[j] = 1u << j; pr[j] = 1u << j; }
    CircTab t;
    for (int l = 0; l < 3; l++) {
        for (int q = 0; q < 10; q++) {
            int g = l * 10 + q, b = 9 - q;          // wire q <-> bit 9-q
            t.m[g] = (unsigned short)pc[b];
            t.r[g] = (unsigned short)pr[b];
        }
        int rr = l % 9 + 1;
        for (int q = 0; q < 10; q++) {
            int c = 9 - q;                           // control bit
            int tt = 9 - ((q + rr) % 10);            // target bit
            pc[c] ^= pc[tt];                         // P' = P * C (column op)
            pr[tt] ^= pr[c];                         // P'^-1 = C * P^-1 (row op)
        }
    }
    for (int j = 0; j < 10; j++) t.fcol[j] = (unsigned short)pc[j];
    return t;
}

// ---------------------------------------------------------------------------
// Launch
// ---------------------------------------------------------------------------
extern "C" void kernel_launch(void* const* d_in, const int* in_sizes, int n_in,
                              void* d_out, int out_size)
{
    const float* inputs = (const float*)d_in[0];
    const float* wEnc   = (const float*)d_in[1];
    const float* wDec   = (const float*)d_in[2];
    const float* W0     = (const float*)d_in[3];
    const float* b0     = (const float*)d_in[4];
    const float* W1     = (const float*)d_in[5];
    const float* b1     = (const float*)d_in[6];
    const float* W2     = (const float*)d_in[7];
    const float* b2     = (const float*)d_in[8];
    const float* W3     = (const float*)d_in[9];
    const float* b3     = (const float*)d_in[10];
    float* outp = (float*)d_out;

    float *bufA = nullptr, *bufB = nullptr, *bias3 = nullptr, *biasC = nullptr,
          *wcPart = nullptr;
    __nv_bfloat16 *actx2 = nullptr, *w0x = nullptr, *w1e = nullptr,
                  *w2x = nullptr, *w3x = nullptr, *wcx = nullptr;
    cudaGetSymbolAddress((void**)&bufA, g_bufA);
    cudaGetSymbolAddress((void**)&bufB, g_bufB);
    cudaGetSymbolAddress((void**)&bias3, g_bias3);
    cudaGetSymbolAddress((void**)&biasC, g_biasC);
    cudaGetSymbolAddress((void**)&wcPart, g_wcPart);
    cudaGetSymbolAddress((void**)&actx2, g_actx2);
    cudaGetSymbolAddress((void**)&w0x, g_w0x);
    cudaGetSymbolAddress((void**)&w1e, g_w1e);
    cudaGetSymbolAddress((void**)&w2x, g_w2x);
    cudaGetSymbolAddress((void**)&w3x, g_w3x);
    cudaGetSymbolAddress((void**)&wcx, g_wcx);

    const CircTab tab = make_circ_tab();

    dim3 blk(256);
    dim3 blkg(128);
    const int GSMEM = NSTAGE * STAGE_BYTES;   // 98304 B dynamic smem (3 stages)
    cudaFuncSetAttribute(gemm_mma,
                         cudaFuncAttributeMaxDynamicSharedMemorySize, GSMEM);

    // ---- Weight prep (per-launch, deterministic) ----
    convert_weight<<<dim3(32, 32), blk>>>(W0, w0x, 1000, 1024, 1024, 1024);
    convert_weight<<<dim3(64, 32), blk>>>(W2, w2x, 2048, 1024, 2048, 1024);
    convert_weight<<<dim3(32, 32), blk>>>(W3, w3x, 1024, 1000, 1024, 1024);
    pad_bias<<<4, blk>>>(b3, bias3, 1000);

    // ---- Fuse W1@W2 -> Wc (split-K=4, deterministic partials + fused reduce)
    convert_act<<<1024 * 2048 / 256, blk>>>(W1, w1e, 2048, 2048);
    gemm_mma<<<dim3(8, 8, 4), blkg, GSMEM>>>(1536, 6144, 1024, 2,
                                             w1e, w2x, bias3, wcPart);
    reduce_convert_weight<<<dim3(32, 32), blk>>>(wcPart, wcx);
    bias_compose<<<4, blk>>>(b1, W2, b2, biasC);        // bc = b1@W2 + b2

    // ---- Main path ----
    // x = inputs @ W0 + b0                       [4096,1024] fp32
    convert_act<<<4096 * 1024 / 256, blk>>>(inputs, actx2, 1000, 1024);
    gemm_mma<<<dim3(8, 32), blkg, GSMEM>>>(3072, 3072, 1024, 0,
                                           actx2, w0x, b0, bufA);
    // x = circuit(x, wEnc) -> ext bf16
    circuit_kernel<<<4096, blk>>>(bufA, wEnc, tab, actx2);
    // x = x @ Wc + bc                            [4096,1024] fp32
    gemm_mma<<<dim3(8, 32), blkg, GSMEM>>>(3072, 3072, 1024, 0,
                                           actx2, wcx, biasC, bufA);
    // x = circuit(x, wDec) -> ext bf16
    circuit_kernel<<<4096, blk>>>(bufA, wDec, tab, actx2);
    // x = x @ W3 + b3                            [4096,1024-padded] fp32
    gemm_mma<<<dim3(8, 32), blkg, GSMEM>>>(3072, 3072, 1024, 0,
                                           actx2, w3x, bias3, bufB);
    // out = |x| / rowsum(|x|)
    abs_norm_kernel<<<4096, blk>>>(bufB, outp);
}

// round 15
// speedup vs baseline: 1.3099x; 1.0648x over previous
#include <cuda_runtime.h>
#include <cuda_bf16.h>
#include <cstdint>
#include <math.h>

// ---------------------------------------------------------------------------
// Scratch (no allocs allowed -> __device__ globals)
// Extended-K encoding dedup: buffers store [hi | lo] (width 2K); the GEMM
// loader remaps k: A wants hi|lo|hi, B wants hi|hi|lo.
// ---------------------------------------------------------------------------
__device__ float g_bufA[4096 * 1024];
__device__ float g_bufB[4096 * 1024];
__device__ __nv_bfloat16 g_actx2[4096 * 2048];   // ext activations [M, 2*1024]
__device__ __nv_bfloat16 g_w0x[1024 * 2048];     // W^T ext [N, 2*K]
__device__ __nv_bfloat16 g_w1e[1024 * 4096];     // W1 ext (act-style) [1024, 2*2048]
__device__ __nv_bfloat16 g_w2x[1024 * 4096];     // W2^T ext [1024, 2*2048]
__device__ __nv_bfloat16 g_w3x[1024 * 2048];
__device__ __nv_bfloat16 g_wcx[1024 * 2048];     // Wc^T ext [1024, 2*1024]
__device__ float g_wcPart[4 * 1024 * 1024];      // split-K partials for Wc
__device__ float g_bias3[1024];
__device__ float g_biasC[1024];

// ---------------------------------------------------------------------------
// PTX helpers (baseline sm_80+ features only: cp.async, ldmatrix, mma.sync)
// ---------------------------------------------------------------------------
__device__ __forceinline__ uint32_t smem_u32(const void* p) {
    uint32_t a;
    asm("{ .reg .u64 t; cvta.to.shared.u64 t, %1; cvt.u32.u64 %0, t; }"
        : "=r"(a) : "l"(p));
    return a;
}

#define CP_ASYNC16(dst_u32, src_ptr)                                          \
    asm volatile("cp.async.cg.shared.global [%0], [%1], 16;"                  \
                 :: "r"(dst_u32), "l"(src_ptr))
#define CP_COMMIT() asm volatile("cp.async.commit_group;" ::: "memory")
#define CP_WAIT(n)  asm volatile("cp.async.wait_group %0;" :: "n"(n) : "memory")

#define LDSM_X4(r0, r1, r2, r3, addr)                                         \
    asm volatile("ldmatrix.sync.aligned.m8n8.x4.shared.b16 {%0,%1,%2,%3}, [%4];" \
                 : "=r"(r0), "=r"(r1), "=r"(r2), "=r"(r3) : "r"(addr))

#define MMA_16816(d, a, b)                                                    \
    asm volatile(                                                             \
        "mma.sync.aligned.m16n8k16.row.col.f32.bf16.bf16.f32 "                \
        "{%0,%1,%2,%3}, {%4,%5,%6,%7}, {%8,%9}, {%0,%1,%2,%3};"               \
        : "+f"((d)[0]), "+f"((d)[1]), "+f"((d)[2]), "+f"((d)[3])              \
        : "r"((a)[0]), "r"((a)[1]), "r"((a)[2]), "r"((a)[3]),                 \
          "r"((b)[0]), "r"((b)[1]))

// ---------------------------------------------------------------------------
// Circuit schedule table (host-computed, structure is weight-independent).
// ---------------------------------------------------------------------------
struct CircTab {
    unsigned short m[30];
    unsigned short r[30];
    unsigned short fcol[10];
};

// ---------------------------------------------------------------------------
// Conversion kernels: fp32 -> dedup ext bf16 [hi | lo] (width 2*K_pad)
// ---------------------------------------------------------------------------
__global__ __launch_bounds__(256) void convert_act(
    const float* __restrict__ in, __nv_bfloat16* __restrict__ out,
    int K_in, int K_pad)
{
    int idx = blockIdx.x * 256 + threadIdx.x;     // over rows * K_pad
    int r = idx / K_pad;
    int k = idx - r * K_pad;
    float x = (k < K_in) ? in[(size_t)r * K_in + k] : 0.0f;
    __nv_bfloat16 hi = __float2bfloat16(x);
    __nv_bfloat16 lo = __float2bfloat16(x - __bfloat162float(hi));
    size_t base = (size_t)r * 2 * K_pad;
    out[base + k] = hi;
    out[base + K_pad + k] = lo;
}

// W [K_in, N_in] row-major  ->  out [N_pad, 2*K_pad] (transposed, hi|lo)
__global__ __launch_bounds__(256) void convert_weight(
    const float* __restrict__ W, __nv_bfloat16* __restrict__ out,
    int K_in, int N_in, int K_pad, int N_pad)
{
    __shared__ float t[32][33];
    int k0 = blockIdx.x * 32, n0 = blockIdx.y * 32;
    int tx = threadIdx.x & 31, ty = threadIdx.x >> 5;   // ty 0..7
    #pragma unroll
    for (int i = 0; i < 32; i += 8) {
        int k = k0 + ty + i, n = n0 + tx;
        t[ty + i][tx] = (k < K_in && n < N_in) ? W[(size_t)k * N_in + n] : 0.0f;
    }
    __syncthreads();
    size_t K2 = 2 * (size_t)K_pad;
    #pragma unroll
    for (int i = 0; i < 32; i += 8) {
        int n = n0 + ty + i, k = k0 + tx;
        if (n < N_pad && k < K_pad) {
            float x = t[tx][ty + i];
            __nv_bfloat16 hi = __float2bfloat16(x);
            __nv_bfloat16 lo = __float2bfloat16(x - __bfloat162float(hi));
            __nv_bfloat16* row = out + (size_t)n * K2;
            row[k] = hi;
            row[K_pad + k] = lo;
        }
    }
}

// Fused: sum 4 split-K partial planes [1024,1024] + transpose + ext bf16.
__global__ __launch_bounds__(256) void reduce_convert_weight(
    const float* __restrict__ p, __nv_bfloat16* __restrict__ out)
{
    __shared__ float t[32][33];
    const int PL = 1024 * 1024;
    int k0 = blockIdx.x * 32, n0 = blockIdx.y * 32;
    int tx = threadIdx.x & 31, ty = threadIdx.x >> 5;   // ty 0..7
    #pragma unroll
    for (int i = 0; i < 32; i += 8) {
        size_t idx = (size_t)(k0 + ty + i) * 1024 + n0 + tx;
        t[ty + i][tx] = (p[idx] + p[idx + PL]) + (p[idx + 2 * PL] + p[idx + 3 * PL]);
    }
    __syncthreads();
    #pragma unroll
    for (int i = 0; i < 32; i += 8) {
        int n = n0 + ty + i, k = k0 + tx;
        float x = t[tx][ty + i];
        __nv_bfloat16 hi = __float2bfloat16(x);
        __nv_bfloat16 lo = __float2bfloat16(x - __bfloat162float(hi));
        __nv_bfloat16* row = out + (size_t)n * 2048;
        row[k] = hi;
        row[1024 + k] = lo;
    }
}

__global__ void pad_bias(const float* __restrict__ b, float* __restrict__ out,
                         int n_in)
{
    int i = blockIdx.x * 256 + threadIdx.x;
    out[i] = (i < n_in) ? b[i] : 0.0f;
}

// bc[j] = sum_k b1[k] * W2[k][j] + b2[j]     (W2: [2048, 1024])
__global__ __launch_bounds__(256) void bias_compose(
    const float* __restrict__ b1, const float* __restrict__ W2,
    const float* __restrict__ b2, float* __restrict__ out)
{
    int j = blockIdx.x * 256 + threadIdx.x;   // 0..1023
    float s0 = 0.0f, s1 = 0.0f, s2 = 0.0f, s3 = 0.0f;
    #pragma unroll 4
    for (int k = 0; k < 2048; k += 4) {
        s0 += b1[k + 0] * W2[(size_t)(k + 0) * 1024 + j];
        s1 += b1[k + 1] * W2[(size_t)(k + 1) * 1024 + j];
        s2 += b1[k + 2] * W2[(size_t)(k + 2) * 1024 + j];
        s3 += b1[k + 3] * W2[(size_t)(k + 3) * 1024 + j];
    }
    out[j] = (s0 + s1) + (s2 + s3) + b2[j];
}

// ---------------------------------------------------------------------------
// mma.sync GEMM over the virtual extended K (Kx = 3*Korig):
//   A virtual blocks: hi | lo | hi    (stored hi|lo, width 2*Korig)
//   B virtual blocks: hi | hi | lo    (stored hi|lo, width 2*Korig)
// Per-chunk remap: kcA = kc>=2*Korig ? kc-2*Korig : kc;
//                  kcB = kc>=Korig   ? kc-Korig   : kc.
// CTA tile 128x128, BK=64 (XOR-swizzled), cp.async double buffer.
// 4 warps (128 threads), warp tile 64x64. grid = (N/128, M/128, Ksplit).
// mode 0: write fp32 C (+bias). mode 2: write fp32 partial plane z (no bias).
// ---------------------------------------------------------------------------
#define TILE_BYTES 16384          // 128 rows * 128 B
#define STAGE_BYTES (2 * TILE_BYTES)

__global__ __launch_bounds__(128, 2) void gemm_mma(
    int Kx, int Korig, int lda, int ldc, int mode,
    const __nv_bfloat16* __restrict__ A, const __nv_bfloat16* __restrict__ B,
    const float* __restrict__ bias, float* __restrict__ C)
{
    extern __shared__ char smem[];
    uint32_t sb = smem_u32(smem);

    const int tid = threadIdx.x;
    const int wid = tid >> 5, lane = tid & 31;
    const int bm = blockIdx.y * 128, bn = blockIdx.x * 128;
    const int koff = blockIdx.z * Kx;
    const int wm = (wid & 1) * 64;
    const int wn = (wid >> 1) * 64;

    float d[4][8][4];
    #pragma unroll
    for (int mt = 0; mt < 4; mt++)
        #pragma unroll
        for (int nt = 0; nt < 8; nt++)
            #pragma unroll
            for (int e = 0; e < 4; e++)
                d[mt][nt][e] = 0.0f;

    const int nch = Kx >> 6;

    auto load_chunk = [&](int ch, int buf) {
        const int kc = koff + (ch << 6);
        const int kcA = (kc >= 2 * Korig) ? kc - 2 * Korig : kc;
        const int kcB = (kc >= Korig) ? kc - Korig : kc;
        uint32_t sA = sb + buf * STAGE_BYTES;
        uint32_t sB = sA + TILE_BYTES;
        #pragma unroll
        for (int it = 0; it < 8; it++) {
            int f = tid + it * 128;
            int r = f >> 3, c16 = f & 7;
            uint32_t off = (uint32_t)(r * 128 + c16 * 16);
            off ^= (off >> 3) & 0x70;
            const __nv_bfloat16* srcA = A + (size_t)(bm + r) * lda + kcA + c16 * 8;
            const __nv_bfloat16* srcB = B + (size_t)(bn + r) * lda + kcB + c16 * 8;
            CP_ASYNC16(sA + off, srcA);
            CP_ASYNC16(sB + off, srcB);
        }
    };

    load_chunk(0, 0);
    CP_COMMIT();

    for (int ch = 0; ch < nch; ch++) {
        const int cur = ch & 1;
        if (ch + 1 < nch) {
            load_chunk(ch + 1, cur ^ 1);
            CP_COMMIT();
            CP_WAIT(1);
        } else {
            CP_WAIT(0);
        }
        __syncthreads();

        uint32_t sA = sb + cur * STAGE_BYTES;
        uint32_t sB = sA + TILE_BYTES;

        #pragma unroll
        for (int s = 0; s < 4; s++) {
            uint32_t a[4][4];
            uint32_t b[8][2];
            #pragma unroll
            for (int mt = 0; mt < 4; mt++) {
                int row = wm + mt * 16 + (lane & 15);
                int colb = s * 32 + ((lane >> 4) & 1) * 16;
                uint32_t off = (uint32_t)(row * 128 + colb);
                off ^= (off >> 3) & 0x70;
                LDSM_X4(a[mt][0], a[mt][1], a[mt][2], a[mt][3], sA + off);
            }
            #pragma unroll
            for (int nt2 = 0; nt2 < 4; nt2++) {
                int row = wn + nt2 * 16 + ((lane >> 4) & 1) * 8 + (lane & 7);
                int colb = s * 32 + ((lane >> 3) & 1) * 16;
                uint32_t off = (uint32_t)(row * 128 + colb);
                off ^= (off >> 3) & 0x70;
                uint32_t r0, r1, r2, r3;
                LDSM_X4(r0, r1, r2, r3, sB + off);
                b[nt2 * 2 + 0][0] = r0; b[nt2 * 2 + 0][1] = r1;
                b[nt2 * 2 + 1][0] = r2; b[nt2 * 2 + 1][1] = r3;
            }
            #pragma unroll
            for (int mt = 0; mt < 4; mt++)
                #pragma unroll
                for (int nt = 0; nt < 8; nt++)
                    MMA_16816(d[mt][nt], a[mt], b[nt]);
        }
        __syncthreads();
    }

    const int er = lane >> 2;
    const int ec = (lane & 3) * 2;
    float* Co = C;
    if (mode == 2) {
        size_t plane = (size_t)(gridDim.x * 128) * (size_t)(gridDim.y * 128);
        Co += (size_t)blockIdx.z * plane;
    }
    #pragma unroll
    for (int nt = 0; nt < 8; nt++) {
        int col = bn + wn + nt * 8 + ec;
        float b0 = 0.0f, b1 = 0.0f;
        if (mode == 0) { b0 = bias[col]; b1 = bias[col + 1]; }
        #pragma unroll
        for (int mt = 0; mt < 4; mt++) {
            int row = bm + wm + mt * 16 + er;
            float2 v0 = make_float2(d[mt][nt][0] + b0, d[mt][nt][1] + b1);
            float2 v1 = make_float2(d[mt][nt][2] + b0, d[mt][nt][3] + b1);
            *reinterpret_cast<float2*>(Co + (size_t)row * ldc + col) = v0;
            *reinterpret_cast<float2*>(Co + (size_t)(row + 8) * ldc + col) = v1;
        }
    }
}

// ---------------------------------------------------------------------------
// Quantum circuit kernel: one block per batch row. CNOTs tracked as GF(2)
// linear map (CircTab). 30 pair-rotations, 30 syncs.
// Writes probs as dedup ext bf16 [hi|lo] (width 2048) for the next GEMM.
// ---------------------------------------------------------------------------
__global__ __launch_bounds__(256) void circuit_kernel(
    const float* __restrict__ x,          // [4096, 1024] fp32
    const float* __restrict__ w,          // [3, 10, 3]
    CircTab tab,
    __nv_bfloat16* __restrict__ out)      // [4096, 2*1024] ext bf16
{
    __shared__ float sre[1024];
    __shared__ float sim[1024];
    __shared__ float Ug[30][4];
    __shared__ float red[8];

    const int row = blockIdx.x;
    const int tid = threadIdx.x;

    if (tid < 30) {
        float phi = w[tid * 3 + 0];
        float th  = w[tid * 3 + 1];
        float om  = w[tid * 3 + 2];
        float s, c;   sincosf(0.5f * th, &s, &c);
        float sa, ca; sincosf(0.5f * (phi + om), &sa, &ca);
        float sb, cb; sincosf(0.5f * (phi - om), &sb, &cb);
        Ug[tid][0] = ca * c;
        Ug[tid][1] = sa * c;
        Ug[tid][2] = cb * s;
        Ug[tid][3] = sb * s;
    }

    float v[4];
    float ss = 0.0f;
    #pragma unroll
    for (int j = 0; j < 4; j++) {
        v[j] = x[(size_t)row * 1024 + tid + j * 256];
        ss += v[j] * v[j];
    }
    #pragma unroll
    for (int o = 16; o > 0; o >>= 1)
        ss += __shfl_xor_sync(0xFFFFFFFFu, ss, o);
    if ((tid & 31) == 0) red[tid >> 5] = ss;
    __syncthreads();
    float tot = 0.0f;
    #pragma unroll
    for (int j = 0; j < 8; j++) tot += red[j];
    float inv = rsqrtf(tot);
    #pragma unroll
    for (int j = 0; j < 4; j++) {
        sre[tid + j * 256] = v[j] * inv;
        sim[tid + j * 256] = 0.0f;
    }
    __syncthreads();

    for (int g = 0; g < 30; g++) {
        const float Am = Ug[g][0], Bm = Ug[g][1];
        const float Cm = Ug[g][2], Dm = Ug[g][3];
        const unsigned m  = tab.m[g];
        const unsigned rr = tab.r[g];
        const unsigned pbm = rr & (0u - rr);       // lowest set bit of rr
        const unsigned lomask = pbm - 1;
        #pragma unroll
        for (int it = 0; it < 2; it++) {
            unsigned p = (unsigned)tid + it * 256; // 0..511
            unsigned lo = p & lomask;
            unsigned y0 = ((p ^ lo) << 1) | lo;    // insert 0 at pivot bit
            unsigned par = __popc(y0 & rr) & 1;
            unsigned i0 = y0 | (par ? pbm : 0u);   // logical bit = 0 side
            unsigned i1 = i0 ^ m;                  // logical bit = 1 partner
            float a0r = sre[i0], a0i = sim[i0];
            float a1r = sre[i1], a1i = sim[i1];
            sre[i0] = Am * a0r + Bm * a0i - Cm * a1r + Dm * a1i;
            sim[i0] = Am * a0i - Bm * a0r - Cm * a1i - Dm * a1r;
            sre[i1] = Cm * a0r + Dm * a0i + Am * a1r - Bm * a1i;
            sim[i1] = Cm * a0i - Dm * a0r + Am * a1i + Bm * a1r;
        }
        __syncthreads();
    }

    // probs at logical index b live at physical P(b) -> ext bf16 (hi|lo)
    size_t base = (size_t)row * 2048;
    #pragma unroll
    for (int j = 0; j < 4; j++) {
        int b = tid + j * 256;
        unsigned phys = 0;
        #pragma unroll
        for (int k2 = 0; k2 < 10; k2++)
            if ((b >> k2) & 1) phys ^= tab.fcol[k2];
        float pre = sre[phys], pim = sim[phys];
        float p = pre * pre + pim * pim;
        __nv_bfloat16 hi = __float2bfloat16(p);
        __nv_bfloat16 lo = __float2bfloat16(p - __bfloat162float(hi));
        out[base + b] = hi;
        out[base + 1024 + b] = lo;
    }
}

// ---------------------------------------------------------------------------
// Final: y = |x| ; y /= rowsum(y)   x: [4096, 1024-strided], out: [4096, 1000]
// ---------------------------------------------------------------------------
__global__ __launch_bounds__(256) void abs_norm_kernel(
    const float* __restrict__ x, float* __restrict__ out)
{
    __shared__ float red[8];
    const int row = blockIdx.x;
    const int tid = threadIdx.x;

    float v[4];
    float ss = 0.0f;
    #pragma unroll
    for (int j = 0; j < 4; j++) {
        int i = tid + j * 256;
        v[j] = (i < 1000) ? fabsf(x[(size_t)row * 1024 + i]) : 0.0f;
        ss += v[j];
    }
    #pragma unroll
    for (int o = 16; o > 0; o >>= 1)
        ss += __shfl_xor_sync(0xFFFFFFFFu, ss, o);
    if ((tid & 31) == 0) red[tid >> 5] = ss;
    __syncthreads();
    float tot = 0.0f;
    #pragma unroll
    for (int j = 0; j < 8; j++) tot += red[j];
    float inv = 1.0f / tot;
    #pragma unroll
    for (int j = 0; j < 4; j++) {
        int i = tid + j * 256;
        if (i < 1000)
            out[(size_t)row * 1000 + i] = v[j] * inv;
    }
}

// ---------------------------------------------------------------------------
// Host: compute circuit schedule (structure-only, weight-independent).
// ---------------------------------------------------------------------------
static CircTab make_circ_tab()
{
    unsigned pc[10], pr[10];
    for (int j = 0; j < 10; j++) { pc[j] = 1u << j; pr[j] = 1u << j; }
    CircTab t;
    for (int l = 0; l < 3; l++) {
        for (int q = 0; q < 10; q++) {
            int g = l * 10 + q, b = 9 - q;          // wire q <-> bit 9-q
            t.m[g] = (unsigned short)pc[b];
            t.r[g] = (unsigned short)pr[b];
        }
        int rr = l % 9 + 1;
        for (int q = 0; q < 10; q++) {
            int c = 9 - q;                           // control bit
            int tt = 9 - ((q + rr) % 10);            // target bit
            pc[c] ^= pc[tt];                         // P' = P * C (column op)
            pr[tt] ^= pr[c];                         // P'^-1 = C * P^-1 (row op)
        }
    }
    for (int j = 0; j < 10; j++) t.fcol[j] = (unsigned short)pc[j];
    return t;
}

// ---------------------------------------------------------------------------
// Launch (ordered so early launch slots hit gemm_mma / circuit for ncu)
// ---------------------------------------------------------------------------
extern "C" void kernel_launch(void* const* d_in, const int* in_sizes, int n_in,
                              void* d_out, int out_size)
{
    const float* inputs = (const float*)d_in[0];
    const float* wEnc   = (const float*)d_in[1];
    const float* wDec   = (const float*)d_in[2];
    const float* W0     = (const float*)d_in[3];
    const float* b0     = (const float*)d_in[4];
    const float* W1     = (const float*)d_in[5];
    const float* b1     = (const float*)d_in[6];
    const float* W2     = (const float*)d_in[7];
    const float* b2     = (const float*)d_in[8];
    const float* W3     = (const float*)d_in[9];
    const float* b3     = (const float*)d_in[10];
    float* outp = (float*)d_out;

    float *bufA = nullptr, *bufB = nullptr, *bias3 = nullptr, *biasC = nullptr,
          *wcPart = nullptr;
    __nv_bfloat16 *actx2 = nullptr, *w0x = nullptr, *w1e = nullptr,
                  *w2x = nullptr, *w3x = nullptr, *wcx = nullptr;
    cudaGetSymbolAddress((void**)&bufA, g_bufA);
    cudaGetSymbolAddress((void**)&bufB, g_bufB);
    cudaGetSymbolAddress((void**)&bias3, g_bias3);
    cudaGetSymbolAddress((void**)&biasC, g_biasC);
    cudaGetSymbolAddress((void**)&wcPart, g_wcPart);
    cudaGetSymbolAddress((void**)&actx2, g_actx2);
    cudaGetSymbolAddress((void**)&w0x, g_w0x);
    cudaGetSymbolAddress((void**)&w1e, g_w1e);
    cudaGetSymbolAddress((void**)&w2x, g_w2x);
    cudaGetSymbolAddress((void**)&w3x, g_w3x);
    cudaGetSymbolAddress((void**)&wcx, g_wcx);

    const CircTab tab = make_circ_tab();

    dim3 blk(256);
    dim3 blkg(128);
    const int GSMEM = 2 * STAGE_BYTES;   // 65536 B dynamic smem (2 stages)
    cudaFuncSetAttribute(gemm_mma,
                         cudaFuncAttributeMaxDynamicSharedMemorySize, GSMEM);

    // 1: W0^T ext
    convert_weight<<<dim3(32, 32), blk>>>(W0, w0x, 1000, 1024, 1024, 1024);
    // 2: inputs ext
    convert_act<<<4096 * 1024 / 256, blk>>>(inputs, actx2, 1000, 1024);
    // 3: b3 padded
    pad_bias<<<4, blk>>>(b3, bias3, 1000);
    // 4: x = inputs @ W0 + b0                    [4096,1024] fp32
    gemm_mma<<<dim3(8, 32), blkg, GSMEM>>>(3072, 1024, 2048, 1024, 0,
                                           actx2, w0x, b0, bufA);
    // 5: x = circuit(x, wEnc) -> ext bf16
    circuit_kernel<<<4096, blk>>>(bufA, wEnc, tab, actx2);
    // 6: W1 ext (act-style)
    convert_act<<<1024 * 2048 / 256, blk>>>(W1, w1e, 2048, 2048);
    // 7: W2^T ext
    convert_weight<<<dim3(64, 32), blk>>>(W2, w2x, 2048, 1024, 2048, 1024);
    // 8: Wc = W1 @ W2 (split-K=4, deterministic partial planes)
    gemm_mma<<<dim3(8, 8, 4), blkg, GSMEM>>>(1536, 2048, 4096, 1024, 2,
                                             w1e, w2x, bias3, wcPart);
    // 9: reduce + transpose + ext
    reduce_convert_weight<<<dim3(32, 32), blk>>>(wcPart, wcx);
    // 10: bc = b1 @ W2 + b2
    bias_compose<<<4, blk>>>(b1, W2, b2, biasC);
    // 11: x = x @ Wc + bc                        [4096,1024] fp32
    gemm_mma<<<dim3(8, 32), blkg, GSMEM>>>(3072, 1024, 2048, 1024, 0,
                                           actx2, wcx, biasC, bufA);
    // 12: x = circuit(x, wDec) -> ext bf16
    circuit_kernel<<<4096, blk>>>(bufA, wDec, tab, actx2);
    // 13: W3^T ext
    convert_weight<<<dim3(32, 32), blk>>>(W3, w3x, 1024, 1000, 1024, 1024);
    // 14: x = x @ W3 + b3                        [4096,1024-padded] fp32
    gemm_mma<<<dim3(8, 32), blkg, GSMEM>>>(3072, 1024, 2048, 1024, 0,
                                           actx2, w3x, bias3, bufB);
    // 15: out = |x| / rowsum(|x|)
    abs_norm_kernel<<<4096, blk>>>(bufB, outp);
}

// round 16
// speedup vs baseline: 1.3886x; 1.0601x over previous
#include <cuda_runtime.h>
#include <cuda_bf16.h>
#include <cstdint>
#include <math.h>

// ---------------------------------------------------------------------------
// Scratch (no allocs allowed -> __device__ globals)
// Extended-K dedup: buffers store [hi | lo] (width 2K); GEMM loader remaps
// the virtual 3K range: A = hi|lo|hi, B = hi|hi|lo.
// ---------------------------------------------------------------------------
__device__ float g_bufA[4096 * 1024];
__device__ float g_bufB[4096 * 1024];
__device__ __nv_bfloat16 g_actx2[4096 * 2048];   // ext activations [M, 2*1024]
__device__ __nv_bfloat16 g_w0x[1024 * 2048];     // W^T ext [N, 2*K]
__device__ __nv_bfloat16 g_w1e[1024 * 4096];     // W1 ext (act-style)
__device__ __nv_bfloat16 g_w2x[1024 * 4096];     // W2^T ext
__device__ __nv_bfloat16 g_w3x[1024 * 2048];
__device__ __nv_bfloat16 g_wcx[1024 * 2048];     // Wc^T ext
__device__ float g_wcPart[4 * 1024 * 1024];      // split-K partials for Wc
__device__ float g_bias3[1024];
__device__ float g_biasC[1024];

// ---------------------------------------------------------------------------
// PTX helpers
// ---------------------------------------------------------------------------
__device__ __forceinline__ uint32_t smem_u32(const void* p) {
    uint32_t a;
    asm("{ .reg .u64 t; cvta.to.shared.u64 t, %1; cvt.u32.u64 %0, t; }"
        : "=r"(a) : "l"(p));
    return a;
}

#define CP_ASYNC16(dst_u32, src_ptr)                                          \
    asm volatile("cp.async.cg.shared.global [%0], [%1], 16;"                  \
                 :: "r"(dst_u32), "l"(src_ptr))
#define CP_COMMIT() asm volatile("cp.async.commit_group;" ::: "memory")
#define CP_WAIT(n)  asm volatile("cp.async.wait_group %0;" :: "n"(n) : "memory")

#define LDSM_X4(r0, r1, r2, r3, addr)                                         \
    asm volatile("ldmatrix.sync.aligned.m8n8.x4.shared.b16 {%0,%1,%2,%3}, [%4];" \
                 : "=r"(r0), "=r"(r1), "=r"(r2), "=r"(r3) : "r"(addr))

#define MMA_16816(d, a, b)                                                    \
    asm volatile(                                                             \
        "mma.sync.aligned.m16n8k16.row.col.f32.bf16.bf16.f32 "                \
        "{%0,%1,%2,%3}, {%4,%5,%6,%7}, {%8,%9}, {%0,%1,%2,%3};"               \
        : "+f"((d)[0]), "+f"((d)[1]), "+f"((d)[2]), "+f"((d)[3])              \
        : "r"((a)[0]), "r"((a)[1]), "r"((a)[2]), "r"((a)[3]),                 \
          "r"((b)[0]), "r"((b)[1]))

// ---------------------------------------------------------------------------
// Circuit schedule (host-computed). Gates paired (2s, 2s+1) within a layer:
// m0/m1 = pair masks (columns of P), r0/r1 = side rows (rows of P^-1),
// L[s][0..7] = GF(2) null-space basis of {r0, r1} -> base-index generator.
// fcol = columns of P for final permutation.
// ---------------------------------------------------------------------------
struct CircTab {
    unsigned short m0[15], m1[15], r0[15], r1[15];
    unsigned short L[15][8];
    unsigned short fcol[10];
};

// ---------------------------------------------------------------------------
// Conversion kernels: fp32 -> dedup ext bf16 [hi | lo]
// ---------------------------------------------------------------------------
__global__ __launch_bounds__(256) void convert_act(
    const float* __restrict__ in, __nv_bfloat16* __restrict__ out,
    int K_in, int K_pad)
{
    int idx = blockIdx.x * 256 + threadIdx.x;
    int r = idx / K_pad;
    int k = idx - r * K_pad;
    float x = (k < K_in) ? in[(size_t)r * K_in + k] : 0.0f;
    __nv_bfloat16 hi = __float2bfloat16(x);
    __nv_bfloat16 lo = __float2bfloat16(x - __bfloat162float(hi));
    size_t base = (size_t)r * 2 * K_pad;
    out[base + k] = hi;
    out[base + K_pad + k] = lo;
}

__global__ __launch_bounds__(256) void convert_weight(
    const float* __restrict__ W, __nv_bfloat16* __restrict__ out,
    int K_in, int N_in, int K_pad, int N_pad)
{
    __shared__ float t[32][33];
    int k0 = blockIdx.x * 32, n0 = blockIdx.y * 32;
    int tx = threadIdx.x & 31, ty = threadIdx.x >> 5;
    #pragma unroll
    for (int i = 0; i < 32; i += 8) {
        int k = k0 + ty + i, n = n0 + tx;
        t[ty + i][tx] = (k < K_in && n < N_in) ? W[(size_t)k * N_in + n] : 0.0f;
    }
    __syncthreads();
    size_t K2 = 2 * (size_t)K_pad;
    #pragma unroll
    for (int i = 0; i < 32; i += 8) {
        int n = n0 + ty + i, k = k0 + tx;
        if (n < N_pad && k < K_pad) {
            float x = t[tx][ty + i];
            __nv_bfloat16 hi = __float2bfloat16(x);
            __nv_bfloat16 lo = __float2bfloat16(x - __bfloat162float(hi));
            __nv_bfloat16* row = out + (size_t)n * K2;
            row[k] = hi;
            row[K_pad + k] = lo;
        }
    }
}

__global__ __launch_bounds__(256) void reduce_convert_weight(
    const float* __restrict__ p, __nv_bfloat16* __restrict__ out)
{
    __shared__ float t[32][33];
    const int PL = 1024 * 1024;
    int k0 = blockIdx.x * 32, n0 = blockIdx.y * 32;
    int tx = threadIdx.x & 31, ty = threadIdx.x >> 5;
    #pragma unroll
    for (int i = 0; i < 32; i += 8) {
        size_t idx = (size_t)(k0 + ty + i) * 1024 + n0 + tx;
        t[ty + i][tx] = (p[idx] + p[idx + PL]) + (p[idx + 2 * PL] + p[idx + 3 * PL]);
    }
    __syncthreads();
    #pragma unroll
    for (int i = 0; i < 32; i += 8) {
        int n = n0 + ty + i, k = k0 + tx;
        float x = t[tx][ty + i];
        __nv_bfloat16 hi = __float2bfloat16(x);
        __nv_bfloat16 lo = __float2bfloat16(x - __bfloat162float(hi));
        __nv_bfloat16* row = out + (size_t)n * 2048;
        row[k] = hi;
        row[1024 + k] = lo;
    }
}

__global__ void pad_bias(const float* __restrict__ b, float* __restrict__ out,
                         int n_in)
{
    int i = blockIdx.x * 256 + threadIdx.x;
    out[i] = (i < n_in) ? b[i] : 0.0f;
}

__global__ __launch_bounds__(256) void bias_compose(
    const float* __restrict__ b1, const float* __restrict__ W2,
    const float* __restrict__ b2, float* __restrict__ out)
{
    int j = blockIdx.x * 256 + threadIdx.x;
    float s0 = 0.0f, s1 = 0.0f, s2 = 0.0f, s3 = 0.0f;
    #pragma unroll 4
    for (int k = 0; k < 2048; k += 4) {
        s0 += b1[k + 0] * W2[(size_t)(k + 0) * 1024 + j];
        s1 += b1[k + 1] * W2[(size_t)(k + 1) * 1024 + j];
        s2 += b1[k + 2] * W2[(size_t)(k + 2) * 1024 + j];
        s3 += b1[k + 3] * W2[(size_t)(k + 3) * 1024 + j];
    }
    out[j] = (s0 + s1) + (s2 + s3) + b2[j];
}

// ---------------------------------------------------------------------------
// mma.sync GEMM, virtual extended K (Kx = 3*Korig), 3-stage cp.async ring,
// ONE __syncthreads per chunk (prefetch of stage (ch+2)%3 issued after the
// barrier; that buffer was last read at ch-1, ordered by this barrier).
// ---------------------------------------------------------------------------
#define TILE_BYTES 16384
#define STAGE_BYTES (2 * TILE_BYTES)
#define NSTAGE 3

__global__ __launch_bounds__(128, 2) void gemm_mma(
    int Kx, int Korig, int lda, int ldc, int mode,
    const __nv_bfloat16* __restrict__ A, const __nv_bfloat16* __restrict__ B,
    const float* __restrict__ bias, float* __restrict__ C)
{
    extern __shared__ char smem[];
    uint32_t sb = smem_u32(smem);

    const int tid = threadIdx.x;
    const int wid = tid >> 5, lane = tid & 31;
    const int bm = blockIdx.y * 128, bn = blockIdx.x * 128;
    const int koff = blockIdx.z * Kx;
    const int wm = (wid & 1) * 64;
    const int wn = (wid >> 1) * 64;

    float d[4][8][4];
    #pragma unroll
    for (int mt = 0; mt < 4; mt++)
        #pragma unroll
        for (int nt = 0; nt < 8; nt++)
            #pragma unroll
            for (int e = 0; e < 4; e++)
                d[mt][nt][e] = 0.0f;

    const int nch = Kx >> 6;

    auto load_chunk = [&](int ch, int buf) {
        const int kc = koff + (ch << 6);
        const int kcA = (kc >= 2 * Korig) ? kc - 2 * Korig : kc;
        const int kcB = (kc >= Korig) ? kc - Korig : kc;
        uint32_t sA = sb + buf * STAGE_BYTES;
        uint32_t sB = sA + TILE_BYTES;
        #pragma unroll
        for (int it = 0; it < 8; it++) {
            int f = tid + it * 128;
            int r = f >> 3, c16 = f & 7;
            uint32_t off = (uint32_t)(r * 128 + c16 * 16);
            off ^= (off >> 3) & 0x70;
            const __nv_bfloat16* srcA = A + (size_t)(bm + r) * lda + kcA + c16 * 8;
            const __nv_bfloat16* srcB = B + (size_t)(bn + r) * lda + kcB + c16 * 8;
            CP_ASYNC16(sA + off, srcA);
            CP_ASYNC16(sB + off, srcB);
        }
    };

    load_chunk(0, 0);
    CP_COMMIT();
    if (nch > 1) {
        load_chunk(1, 1);
        CP_COMMIT();
    }

    for (int ch = 0; ch < nch; ch++) {
        const int cur = ch % NSTAGE;
        if (ch + 1 < nch) { CP_WAIT(1); } else { CP_WAIT(0); }
        __syncthreads();
        if (ch + 2 < nch) {
            load_chunk(ch + 2, (ch + 2) % NSTAGE);
            CP_COMMIT();
        }

        uint32_t sA = sb + cur * STAGE_BYTES;
        uint32_t sB = sA + TILE_BYTES;

        #pragma unroll
        for (int s = 0; s < 4; s++) {
            uint32_t a[4][4];
            uint32_t b[8][2];
            #pragma unroll
            for (int mt = 0; mt < 4; mt++) {
                int row = wm + mt * 16 + (lane & 15);
                int colb = s * 32 + ((lane >> 4) & 1) * 16;
                uint32_t off = (uint32_t)(row * 128 + colb);
                off ^= (off >> 3) & 0x70;
                LDSM_X4(a[mt][0], a[mt][1], a[mt][2], a[mt][3], sA + off);
            }
            #pragma unroll
            for (int nt2 = 0; nt2 < 4; nt2++) {
                int row = wn + nt2 * 16 + ((lane >> 4) & 1) * 8 + (lane & 7);
                int colb = s * 32 + ((lane >> 3) & 1) * 16;
                uint32_t off = (uint32_t)(row * 128 + colb);
                off ^= (off >> 3) & 0x70;
                uint32_t r0, r1, r2, r3;
                LDSM_X4(r0, r1, r2, r3, sB + off);
                b[nt2 * 2 + 0][0] = r0; b[nt2 * 2 + 0][1] = r1;
                b[nt2 * 2 + 1][0] = r2; b[nt2 * 2 + 1][1] = r3;
            }
            #pragma unroll
            for (int mt = 0; mt < 4; mt++)
                #pragma unroll
                for (int nt = 0; nt < 8; nt++)
                    MMA_16816(d[mt][nt], a[mt], b[nt]);
        }
        // no trailing sync: next iteration's barrier orders buffer reuse
    }

    const int er = lane >> 2;
    const int ec = (lane & 3) * 2;
    float* Co = C;
    if (mode == 2) {
        size_t plane = (size_t)(gridDim.x * 128) * (size_t)(gridDim.y * 128);
        Co += (size_t)blockIdx.z * plane;
    }
    #pragma unroll
    for (int nt = 0; nt < 8; nt++) {
        int col = bn + wn + nt * 8 + ec;
        float b0 = 0.0f, b1 = 0.0f;
        if (mode == 0) { b0 = bias[col]; b1 = bias[col + 1]; }
        #pragma unroll
        for (int mt = 0; mt < 4; mt++) {
            int row = bm + wm + mt * 16 + er;
            float2 v0 = make_float2(d[mt][nt][0] + b0, d[mt][nt][1] + b1);
            float2 v1 = make_float2(d[mt][nt][2] + b0, d[mt][nt][3] + b1);
            *reinterpret_cast<float2*>(Co + (size_t)row * ldc + col) = v0;
            *reinterpret_cast<float2*>(Co + (size_t)(row + 8) * ldc + col) = v1;
        }
    }
}

// ---------------------------------------------------------------------------
// Quantum circuit kernel v3: rotation pairs fused into 4-groups.
// Stage s applies gates g0=2s, g1=2s+1 (same layer -> same P):
//   base i0 from 8-bit p via GF(2) basis L (guarantees <r0,i0>=<r1,i0>=0),
//   group {i0, i0^m0, i0^m1, i0^m0^m1}; both gates applied in registers.
// 15 syncs total; half the smem traffic of the per-gate version.
// ---------------------------------------------------------------------------
__global__ __launch_bounds__(256) void circuit_kernel(
    const float* __restrict__ x,          // [4096, 1024] fp32
    const float* __restrict__ w,          // [3, 10, 3]
    CircTab tab,
    __nv_bfloat16* __restrict__ out)      // [4096, 2*1024] ext bf16
{
    __shared__ float sre[1024];
    __shared__ float sim[1024];
    __shared__ float Ug[30][4];
    __shared__ float red[8];

    const int row = blockIdx.x;
    const int tid = threadIdx.x;

    if (tid < 30) {
        float phi = w[tid * 3 + 0];
        float th  = w[tid * 3 + 1];
        float om  = w[tid * 3 + 2];
        float s, c;   sincosf(0.5f * th, &s, &c);
        float sa, ca; sincosf(0.5f * (phi + om), &sa, &ca);
        float sb, cb; sincosf(0.5f * (phi - om), &sb, &cb);
        Ug[tid][0] = ca * c;
        Ug[tid][1] = sa * c;
        Ug[tid][2] = cb * s;
        Ug[tid][3] = sb * s;
    }

    float v[4];
    float ss = 0.0f;
    #pragma unroll
    for (int j = 0; j < 4; j++) {
        v[j] = x[(size_t)row * 1024 + tid + j * 256];
        ss += v[j] * v[j];
    }
    #pragma unroll
    for (int o = 16; o > 0; o >>= 1)
        ss += __shfl_xor_sync(0xFFFFFFFFu, ss, o);
    if ((tid & 31) == 0) red[tid >> 5] = ss;
    __syncthreads();
    float tot = 0.0f;
    #pragma unroll
    for (int j = 0; j < 8; j++) tot += red[j];
    float inv = rsqrtf(tot);
    #pragma unroll
    for (int j = 0; j < 4; j++) {
        sre[tid + j * 256] = v[j] * inv;
        sim[tid + j * 256] = 0.0f;
    }
    __syncthreads();

    const unsigned p = (unsigned)tid;     // 8-bit group selector (0..255)

    for (int s = 0; s < 15; s++) {
        const unsigned m0 = tab.m0[s], m1 = tab.m1[s];

        // base index from GF(2) basis
        unsigned i0 = 0;
        #pragma unroll
        for (int bIdx = 0; bIdx < 8; bIdx++)
            if ((p >> bIdx) & 1) i0 ^= tab.L[s][bIdx];

        const unsigned i10 = i0 ^ m0;
        const unsigned i01 = i0 ^ m1;
        const unsigned i11 = i10 ^ m1;

        float r00 = sre[i0],  q00 = sim[i0];
        float r10 = sre[i10], q10 = sim[i10];
        float r01 = sre[i01], q01 = sim[i01];
        float r11 = sre[i11], q11 = sim[i11];

        // gate 0 on pairs (00,10) and (01,11)
        {
            const float Am = Ug[2 * s][0], Bm = Ug[2 * s][1];
            const float Cm = Ug[2 * s][2], Dm = Ug[2 * s][3];
            float nr0 = Am * r00 + Bm * q00 - Cm * r10 + Dm * q10;
            float nq0 = Am * q00 - Bm * r00 - Cm * q10 - Dm * r10;
            float nr1 = Cm * r00 + Dm * q00 + Am * r10 - Bm * q10;
            float nq1 = Cm * q00 - Dm * r00 + Am * q10 + Bm * r10;
            r00 = nr0; q00 = nq0; r10 = nr1; q10 = nq1;
            nr0 = Am * r01 + Bm * q01 - Cm * r11 + Dm * q11;
            nq0 = Am * q01 - Bm * r01 - Cm * q11 - Dm * r11;
            nr1 = Cm * r01 + Dm * q01 + Am * r11 - Bm * q11;
            nq1 = Cm * q01 - Dm * r01 + Am * q11 + Bm * r11;
            r01 = nr0; q01 = nq0; r11 = nr1; q11 = nq1;
        }
        // gate 1 on pairs (00,01) and (10,11)
        {
            const float Am = Ug[2 * s + 1][0], Bm = Ug[2 * s + 1][1];
            const float Cm = Ug[2 * s + 1][2], Dm = Ug[2 * s + 1][3];
            float nr0 = Am * r00 + Bm * q00 - Cm * r01 + Dm * q01;
            float nq0 = Am * q00 - Bm * r00 - Cm * q01 - Dm * r01;
            float nr1 = Cm * r00 + Dm * q00 + Am * r01 - Bm * q01;
            float nq1 = Cm * q00 - Dm * r00 + Am * q01 + Bm * r01;
            r00 = nr0; q00 = nq0; r01 = nr1; q01 = nq1;
            nr0 = Am * r10 + Bm * q10 - Cm * r11 + Dm * q11;
            nq0 = Am * q10 - Bm * r10 - Cm * q11 - Dm * r11;
            nr1 = Cm * r10 + Dm * q10 + Am * r11 - Bm * q11;
            nq1 = Cm * q10 - Dm * r10 + Am * q11 + Bm * r11;
            r10 = nr0; q10 = nq0; r11 = nr1; q11 = nq1;
        }

        sre[i0]  = r00; sim[i0]  = q00;
        sre[i10] = r10; sim[i10] = q10;
        sre[i01] = r01; sim[i01] = q01;
        sre[i11] = r11; sim[i11] = q11;
        __syncthreads();
    }

    // probs at logical index b live at physical P(b) -> ext bf16 (hi|lo)
    size_t base = (size_t)row * 2048;
    #pragma unroll
    for (int j = 0; j < 4; j++) {
        int b = tid + j * 256;
        unsigned phys = 0;
        #pragma unroll
        for (int k2 = 0; k2 < 10; k2++)
            if ((b >> k2) & 1) phys ^= tab.fcol[k2];
        float pre = sre[phys], pim = sim[phys];
        float pp = pre * pre + pim * pim;
        __nv_bfloat16 hi = __float2bfloat16(pp);
        __nv_bfloat16 lo = __float2bfloat16(pp - __bfloat162float(hi));
        out[base + b] = hi;
        out[base + 1024 + b] = lo;
    }
}

// ---------------------------------------------------------------------------
// Final: y = |x| ; y /= rowsum(y)
// ---------------------------------------------------------------------------
__global__ __launch_bounds__(256) void abs_norm_kernel(
    const float* __restrict__ x, float* __restrict__ out)
{
    __shared__ float red[8];
    const int row = blockIdx.x;
    const int tid = threadIdx.x;

    float v[4];
    float ss = 0.0f;
    #pragma unroll
    for (int j = 0; j < 4; j++) {
        int i = tid + j * 256;
        v[j] = (i < 1000) ? fabsf(x[(size_t)row * 1024 + i]) : 0.0f;
        ss += v[j];
    }
    #pragma unroll
    for (int o = 16; o > 0; o >>= 1)
        ss += __shfl_xor_sync(0xFFFFFFFFu, ss, o);
    if ((tid & 31) == 0) red[tid >> 5] = ss;
    __syncthreads();
    float tot = 0.0f;
    #pragma unroll
    for (int j = 0; j < 8; j++) tot += red[j];
    float inv = 1.0f / tot;
    #pragma unroll
    for (int j = 0; j < 4; j++) {
        int i = tid + j * 256;
        if (i < 1000)
            out[(size_t)row * 1000 + i] = v[j] * inv;
    }
}

// ---------------------------------------------------------------------------
// Host: circuit schedule. Rows r are rows of P^{-1}; masks m are columns of
// P. For each gate pair (same layer), build the 8-dim GF(2) null-space basis.
// ---------------------------------------------------------------------------
static int ctz10(unsigned x) { int i = 0; while (!((x >> i) & 1)) i++; return i; }

static CircTab make_circ_tab()
{
    unsigned pc[10], pr[10];
    unsigned gm[30], gr[30];
    for (int j = 0; j < 10; j++) { pc[j] = 1u << j; pr[j] = 1u << j; }
    for (int l = 0; l < 3; l++) {
        for (int q = 0; q < 10; q++) {
            int g = l * 10 + q, b = 9 - q;
            gm[g] = pc[b];
            gr[g] = pr[b];
        }
        int rr = l % 9 + 1;
        for (int q = 0; q < 10; q++) {
            int c = 9 - q;
            int tt = 9 - ((q + rr) % 10);
            pc[c] ^= pc[tt];
            pr[tt] ^= pr[c];
        }
    }
    CircTab t;
    for (int j = 0; j < 10; j++) t.fcol[j] = (unsigned short)pc[j];
    for (int s = 0; s < 15; s++) {
        unsigned r0 = gr[2 * s], r1 = gr[2 * s + 1];
        t.m0[s] = (unsigned short)gm[2 * s];
        t.m1[s] = (unsigned short)gm[2 * s + 1];
        t.r0[s] = (unsigned short)r0;
        t.r1[s] = (unsigned short)r1;
        // Gaussian elimination for independent pivots
        unsigned a = r0, b = r1;
        int p0 = ctz10(a);
        if ((b >> p0) & 1) b ^= a;
        int p1 = ctz10(b);
        if ((a >> p1) & 1) a ^= b;
        int idx = 0;
        for (int bit = 0; bit < 10; bit++) {
            if (bit == p0 || bit == p1) continue;
            unsigned vv = 1u << bit;
            if (__builtin_popcount(vv & a) & 1) vv ^= 1u << p0;
            if (__builtin_popcount(vv & b) & 1) vv ^= 1u << p1;
            t.L[s][idx++] = (unsigned short)vv;
        }
    }
    return t;
}

// ---------------------------------------------------------------------------
// Launch
// ---------------------------------------------------------------------------
extern "C" void kernel_launch(void* const* d_in, const int* in_sizes, int n_in,
                              void* d_out, int out_size)
{
    const float* inputs = (const float*)d_in[0];
    const float* wEnc   = (const float*)d_in[1];
    const float* wDec   = (const float*)d_in[2];
    const float* W0     = (const float*)d_in[3];
    const float* b0     = (const float*)d_in[4];
    const float* W1     = (const float*)d_in[5];
    const float* b1     = (const float*)d_in[6];
    const float* W2     = (const float*)d_in[7];
    const float* b2     = (const float*)d_in[8];
    const float* W3     = (const float*)d_in[9];
    const float* b3     = (const float*)d_in[10];
    float* outp = (float*)d_out;

    float *bufA = nullptr, *bufB = nullptr, *bias3 = nullptr, *biasC = nullptr,
          *wcPart = nullptr;
    __nv_bfloat16 *actx2 = nullptr, *w0x = nullptr, *w1e = nullptr,
                  *w2x = nullptr, *w3x = nullptr, *wcx = nullptr;
    cudaGetSymbolAddress((void**)&bufA, g_bufA);
    cudaGetSymbolAddress((void**)&bufB, g_bufB);
    cudaGetSymbolAddress((void**)&bias3, g_bias3);
    cudaGetSymbolAddress((void**)&biasC, g_biasC);
    cudaGetSymbolAddress((void**)&wcPart, g_wcPart);
    cudaGetSymbolAddress((void**)&actx2, g_actx2);
    cudaGetSymbolAddress((void**)&w0x, g_w0x);
    cudaGetSymbolAddress((void**)&w1e, g_w1e);
    cudaGetSymbolAddress((void**)&w2x, g_w2x);
    cudaGetSymbolAddress((void**)&w3x, g_w3x);
    cudaGetSymbolAddress((void**)&wcx, g_wcx);

    const CircTab tab = make_circ_tab();

    dim3 blk(256);
    dim3 blkg(128);
    const int GSMEM = NSTAGE * STAGE_BYTES;   // 98304 B dynamic smem
    cudaFuncSetAttribute(gemm_mma,
                         cudaFuncAttributeMaxDynamicSharedMemorySize, GSMEM);

    // 1: W0^T ext
    convert_weight<<<dim3(32, 32), blk>>>(W0, w0x, 1000, 1024, 1024, 1024);
    // 2: inputs ext
    convert_act<<<4096 * 1024 / 256, blk>>>(inputs, actx2, 1000, 1024);
    // 3: b3 padded
    pad_bias<<<4, blk>>>(b3, bias3, 1000);
    // 4: x = inputs @ W0 + b0
    gemm_mma<<<dim3(8, 32), blkg, GSMEM>>>(3072, 1024, 2048, 1024, 0,
                                           actx2, w0x, b0, bufA);
    // 5: x = circuit(x, wEnc) -> ext bf16
    circuit_kernel<<<4096, blk>>>(bufA, wEnc, tab, actx2);
    // 6: W1 ext (act-style)
    convert_act<<<1024 * 2048 / 256, blk>>>(W1, w1e, 2048, 2048);
    // 7: W2^T ext
    convert_weight<<<dim3(64, 32), blk>>>(W2, w2x, 2048, 1024, 2048, 1024);
    // 8: Wc = W1 @ W2 (split-K=4)
    gemm_mma<<<dim3(8, 8, 4), blkg, GSMEM>>>(1536, 2048, 4096, 1024, 2,
                                             w1e, w2x, bias3, wcPart);
    // 9: reduce + transpose + ext
    reduce_convert_weight<<<dim3(32, 32), blk>>>(wcPart, wcx);
    // 10: bc = b1 @ W2 + b2
    bias_compose<<<4, blk>>>(b1, W2, b2, biasC);
    // 11: x = x @ Wc + bc
    gemm_mma<<<dim3(8, 32), blkg, GSMEM>>>(3072, 1024, 2048, 1024, 0,
                                           actx2, wcx, biasC, bufA);
    // 12: x = circuit(x, wDec) -> ext bf16
    circuit_kernel<<<4096, blk>>>(bufA, wDec, tab, actx2);
    // 13: W3^T ext
    convert_weight<<<dim3(32, 32), blk>>>(W3, w3x, 1024, 1000, 1024, 1024);
    // 14: x = x @ W3 + b3
    gemm_mma<<<dim3(8, 32), blkg, GSMEM>>>(3072, 1024, 2048, 1024, 0,
                                           actx2, w3x, bias3, bufB);
    // 15: out = |x| / rowsum(|x|)
    abs_norm_kernel<<<4096, blk>>>(bufB, outp);
}

// round 17
// speedup vs baseline: 1.6066x; 1.1569x over previous
#include <cuda_runtime.h>
#include <cuda_bf16.h>
#include <cstdint>
#include <math.h>

// ---------------------------------------------------------------------------
// Scratch (no allocs allowed -> __device__ globals)
// Extended-K dedup: buffers store [hi | lo] (width 2K); GEMM loader remaps
// the virtual 3K range: A = hi|lo|hi, B = hi|hi|lo.
// ---------------------------------------------------------------------------
__device__ float g_bufA[4096 * 1024];
__device__ float g_bufB[4096 * 1024];
__device__ __nv_bfloat16 g_actx2[4096 * 2048];   // ext activations [M, 2*1024]
__device__ __nv_bfloat16 g_w0x[1024 * 2048];     // W^T ext [N, 2*K]
__device__ __nv_bfloat16 g_w1e[1024 * 4096];     // W1 ext (act-style)
__device__ __nv_bfloat16 g_w2x[1024 * 4096];     // W2^T ext
__device__ __nv_bfloat16 g_w3x[1024 * 2048];
__device__ __nv_bfloat16 g_wcx[1024 * 2048];     // Wc^T ext
__device__ float g_wcPart[4 * 1024 * 1024];      // split-K partials for Wc
__device__ float g_bias3[1024];
__device__ float g_biasC[1024];

// ---------------------------------------------------------------------------
// PTX helpers
// ---------------------------------------------------------------------------
__device__ __forceinline__ uint32_t smem_u32(const void* p) {
    uint32_t a;
    asm("{ .reg .u64 t; cvta.to.shared.u64 t, %1; cvt.u32.u64 %0, t; }"
        : "=r"(a) : "l"(p));
    return a;
}

#define CP_ASYNC16(dst_u32, src_ptr)                                          \
    asm volatile("cp.async.cg.shared.global [%0], [%1], 16;"                  \
                 :: "r"(dst_u32), "l"(src_ptr))
#define CP_COMMIT() asm volatile("cp.async.commit_group;" ::: "memory")
#define CP_WAIT(n)  asm volatile("cp.async.wait_group %0;" :: "n"(n) : "memory")

#define LDSM_X4(r0, r1, r2, r3, addr)                                         \
    asm volatile("ldmatrix.sync.aligned.m8n8.x4.shared.b16 {%0,%1,%2,%3}, [%4];" \
                 : "=r"(r0), "=r"(r1), "=r"(r2), "=r"(r3) : "r"(addr))

#define MMA_16816(d, a, b)                                                    \
    asm volatile(                                                             \
        "mma.sync.aligned.m16n8k16.row.col.f32.bf16.bf16.f32 "                \
        "{%0,%1,%2,%3}, {%4,%5,%6,%7}, {%8,%9}, {%0,%1,%2,%3};"               \
        : "+f"((d)[0]), "+f"((d)[1]), "+f"((d)[2]), "+f"((d)[3])              \
        : "r"((a)[0]), "r"((a)[1]), "r"((a)[2]), "r"((a)[3]),                 \
          "r"((b)[0]), "r"((b)[1]))

// ---------------------------------------------------------------------------
// Circuit schedule (host-computed). Gates paired (2s, 2s+1) within a layer.
// ---------------------------------------------------------------------------
struct CircTab {
    unsigned short m0[15], m1[15], r0[15], r1[15];
    unsigned short L[15][8];
    unsigned short fcol[10];
};

// ---------------------------------------------------------------------------
// Conversion kernels: fp32 -> dedup ext bf16 [hi | lo]
// ---------------------------------------------------------------------------
__global__ __launch_bounds__(256) void convert_act(
    const float* __restrict__ in, __nv_bfloat16* __restrict__ out,
    int K_in, int K_pad)
{
    int idx = blockIdx.x * 256 + threadIdx.x;
    int r = idx / K_pad;
    int k = idx - r * K_pad;
    float x = (k < K_in) ? in[(size_t)r * K_in + k] : 0.0f;
    __nv_bfloat16 hi = __float2bfloat16(x);
    __nv_bfloat16 lo = __float2bfloat16(x - __bfloat162float(hi));
    size_t base = (size_t)r * 2 * K_pad;
    out[base + k] = hi;
    out[base + K_pad + k] = lo;
}

__global__ __launch_bounds__(256) void convert_weight(
    const float* __restrict__ W, __nv_bfloat16* __restrict__ out,
    int K_in, int N_in, int K_pad, int N_pad)
{
    __shared__ float t[32][33];
    int k0 = blockIdx.x * 32, n0 = blockIdx.y * 32;
    int tx = threadIdx.x & 31, ty = threadIdx.x >> 5;
    #pragma unroll
    for (int i = 0; i < 32; i += 8) {
        int k = k0 + ty + i, n = n0 + tx;
        t[ty + i][tx] = (k < K_in && n < N_in) ? W[(size_t)k * N_in + n] : 0.0f;
    }
    __syncthreads();
    size_t K2 = 2 * (size_t)K_pad;
    #pragma unroll
    for (int i = 0; i < 32; i += 8) {
        int n = n0 + ty + i, k = k0 + tx;
        if (n < N_pad && k < K_pad) {
            float x = t[tx][ty + i];
            __nv_bfloat16 hi = __float2bfloat16(x);
            __nv_bfloat16 lo = __float2bfloat16(x - __bfloat162float(hi));
            __nv_bfloat16* row = out + (size_t)n * K2;
            row[k] = hi;
            row[K_pad + k] = lo;
        }
    }
}

__global__ __launch_bounds__(256) void reduce_convert_weight(
    const float* __restrict__ p, __nv_bfloat16* __restrict__ out)
{
    __shared__ float t[32][33];
    const int PL = 1024 * 1024;
    int k0 = blockIdx.x * 32, n0 = blockIdx.y * 32;
    int tx = threadIdx.x & 31, ty = threadIdx.x >> 5;
    #pragma unroll
    for (int i = 0; i < 32; i += 8) {
        size_t idx = (size_t)(k0 + ty + i) * 1024 + n0 + tx;
        t[ty + i][tx] = (p[idx] + p[idx + PL]) + (p[idx + 2 * PL] + p[idx + 3 * PL]);
    }
    __syncthreads();
    #pragma unroll
    for (int i = 0; i < 32; i += 8) {
        int n = n0 + ty + i, k = k0 + tx;
        float x = t[tx][ty + i];
        __nv_bfloat16 hi = __float2bfloat16(x);
        __nv_bfloat16 lo = __float2bfloat16(x - __bfloat162float(hi));
        __nv_bfloat16* row = out + (size_t)n * 2048;
        row[k] = hi;
        row[1024 + k] = lo;
    }
}

__global__ void pad_bias(const float* __restrict__ b, float* __restrict__ out,
                         int n_in)
{
    int i = blockIdx.x * 256 + threadIdx.x;
    out[i] = (i < n_in) ? b[i] : 0.0f;
}

__global__ __launch_bounds__(256) void bias_compose(
    const float* __restrict__ b1, const float* __restrict__ W2,
    const float* __restrict__ b2, float* __restrict__ out)
{
    int j = blockIdx.x * 256 + threadIdx.x;
    float s0 = 0.0f, s1 = 0.0f, s2 = 0.0f, s3 = 0.0f;
    #pragma unroll 4
    for (int k = 0; k < 2048; k += 4) {
        s0 += b1[k + 0] * W2[(size_t)(k + 0) * 1024 + j];
        s1 += b1[k + 1] * W2[(size_t)(k + 1) * 1024 + j];
        s2 += b1[k + 2] * W2[(size_t)(k + 2) * 1024 + j];
        s3 += b1[k + 3] * W2[(size_t)(k + 3) * 1024 + j];
    }
    out[j] = (s0 + s1) + (s2 + s3) + b2[j];
}

// ---------------------------------------------------------------------------
// mma.sync GEMM, virtual extended K (Kx = 3*Korig), 3-stage cp.async ring,
// one __syncthreads per chunk.
// ---------------------------------------------------------------------------
#define TILE_BYTES 16384
#define STAGE_BYTES (2 * TILE_BYTES)
#define NSTAGE 3

__global__ __launch_bounds__(128, 2) void gemm_mma(
    int Kx, int Korig, int lda, int ldc, int mode,
    const __nv_bfloat16* __restrict__ A, const __nv_bfloat16* __restrict__ B,
    const float* __restrict__ bias, float* __restrict__ C)
{
    extern __shared__ char smem[];
    uint32_t sb = smem_u32(smem);

    const int tid = threadIdx.x;
    const int wid = tid >> 5, lane = tid & 31;
    const int bm = blockIdx.y * 128, bn = blockIdx.x * 128;
    const int koff = blockIdx.z * Kx;
    const int wm = (wid & 1) * 64;
    const int wn = (wid >> 1) * 64;

    float d[4][8][4];
    #pragma unroll
    for (int mt = 0; mt < 4; mt++)
        #pragma unroll
        for (int nt = 0; nt < 8; nt++)
            #pragma unroll
            for (int e = 0; e < 4; e++)
                d[mt][nt][e] = 0.0f;

    const int nch = Kx >> 6;

    auto load_chunk = [&](int ch, int buf) {
        const int kc = koff + (ch << 6);
        const int kcA = (kc >= 2 * Korig) ? kc - 2 * Korig : kc;
        const int kcB = (kc >= Korig) ? kc - Korig : kc;
        uint32_t sA = sb + buf * STAGE_BYTES;
        uint32_t sB = sA + TILE_BYTES;
        #pragma unroll
        for (int it = 0; it < 8; it++) {
            int f = tid + it * 128;
            int r = f >> 3, c16 = f & 7;
            uint32_t off = (uint32_t)(r * 128 + c16 * 16);
            off ^= (off >> 3) & 0x70;
            const __nv_bfloat16* srcA = A + (size_t)(bm + r) * lda + kcA + c16 * 8;
            const __nv_bfloat16* srcB = B + (size_t)(bn + r) * lda + kcB + c16 * 8;
            CP_ASYNC16(sA + off, srcA);
            CP_ASYNC16(sB + off, srcB);
        }
    };

    load_chunk(0, 0);
    CP_COMMIT();
    if (nch > 1) {
        load_chunk(1, 1);
        CP_COMMIT();
    }

    for (int ch = 0; ch < nch; ch++) {
        const int cur = ch % NSTAGE;
        if (ch + 1 < nch) { CP_WAIT(1); } else { CP_WAIT(0); }
        __syncthreads();
        if (ch + 2 < nch) {
            load_chunk(ch + 2, (ch + 2) % NSTAGE);
            CP_COMMIT();
        }

        uint32_t sA = sb + cur * STAGE_BYTES;
        uint32_t sB = sA + TILE_BYTES;

        #pragma unroll
        for (int s = 0; s < 4; s++) {
            uint32_t a[4][4];
            uint32_t b[8][2];
            #pragma unroll
            for (int mt = 0; mt < 4; mt++) {
                int row = wm + mt * 16 + (lane & 15);
                int colb = s * 32 + ((lane >> 4) & 1) * 16;
                uint32_t off = (uint32_t)(row * 128 + colb);
                off ^= (off >> 3) & 0x70;
                LDSM_X4(a[mt][0], a[mt][1], a[mt][2], a[mt][3], sA + off);
            }
            #pragma unroll
            for (int nt2 = 0; nt2 < 4; nt2++) {
                int row = wn + nt2 * 16 + ((lane >> 4) & 1) * 8 + (lane & 7);
                int colb = s * 32 + ((lane >> 3) & 1) * 16;
                uint32_t off = (uint32_t)(row * 128 + colb);
                off ^= (off >> 3) & 0x70;
                uint32_t r0, r1, r2, r3;
                LDSM_X4(r0, r1, r2, r3, sB + off);
                b[nt2 * 2 + 0][0] = r0; b[nt2 * 2 + 0][1] = r1;
                b[nt2 * 2 + 1][0] = r2; b[nt2 * 2 + 1][1] = r3;
            }
            #pragma unroll
            for (int mt = 0; mt < 4; mt++)
                #pragma unroll
                for (int nt = 0; nt < 8; nt++)
                    MMA_16816(d[mt][nt], a[mt], b[nt]);
        }
    }

    const int er = lane >> 2;
    const int ec = (lane & 3) * 2;
    float* Co = C;
    if (mode == 2) {
        size_t plane = (size_t)(gridDim.x * 128) * (size_t)(gridDim.y * 128);
        Co += (size_t)blockIdx.z * plane;
    }
    #pragma unroll
    for (int nt = 0; nt < 8; nt++) {
        int col = bn + wn + nt * 8 + ec;
        float b0 = 0.0f, b1 = 0.0f;
        if (mode == 0) { b0 = bias[col]; b1 = bias[col + 1]; }
        #pragma unroll
        for (int mt = 0; mt < 4; mt++) {
            int row = bm + wm + mt * 16 + er;
            float2 v0 = make_float2(d[mt][nt][0] + b0, d[mt][nt][1] + b1);
            float2 v1 = make_float2(d[mt][nt][2] + b0, d[mt][nt][3] + b1);
            *reinterpret_cast<float2*>(Co + (size_t)row * ldc + col) = v0;
            *reinterpret_cast<float2*>(Co + (size_t)(row + 8) * ldc + col) = v1;
        }
    }
}

// ---------------------------------------------------------------------------
// Quantum circuit kernel v3: rotation pairs fused into 4-groups. 15 syncs.
// ---------------------------------------------------------------------------
__global__ __launch_bounds__(256) void circuit_kernel(
    const float* __restrict__ x,          // [4096, 1024] fp32
    const float* __restrict__ w,          // [3, 10, 3]
    CircTab tab,
    __nv_bfloat16* __restrict__ out)      // [4096, 2*1024] ext bf16
{
    __shared__ float sre[1024];
    __shared__ float sim[1024];
    __shared__ float Ug[30][4];
    __shared__ float red[8];

    const int row = blockIdx.x;
    const int tid = threadIdx.x;

    if (tid < 30) {
        float phi = w[tid * 3 + 0];
        float th  = w[tid * 3 + 1];
        float om  = w[tid * 3 + 2];
        float s, c;   sincosf(0.5f * th, &s, &c);
        float sa, ca; sincosf(0.5f * (phi + om), &sa, &ca);
        float sb, cb; sincosf(0.5f * (phi - om), &sb, &cb);
        Ug[tid][0] = ca * c;
        Ug[tid][1] = sa * c;
        Ug[tid][2] = cb * s;
        Ug[tid][3] = sb * s;
    }

    float v[4];
    float ss = 0.0f;
    #pragma unroll
    for (int j = 0; j < 4; j++) {
        v[j] = x[(size_t)row * 1024 + tid + j * 256];
        ss += v[j] * v[j];
    }
    #pragma unroll
    for (int o = 16; o > 0; o >>= 1)
        ss += __shfl_xor_sync(0xFFFFFFFFu, ss, o);
    if ((tid & 31) == 0) red[tid >> 5] = ss;
    __syncthreads();
    float tot = 0.0f;
    #pragma unroll
    for (int j = 0; j < 8; j++) tot += red[j];
    float inv = rsqrtf(tot);
    #pragma unroll
    for (int j = 0; j < 4; j++) {
        sre[tid + j * 256] = v[j] * inv;
        sim[tid + j * 256] = 0.0f;
    }
    __syncthreads();

    const unsigned p = (unsigned)tid;

    for (int s = 0; s < 15; s++) {
        const unsigned m0 = tab.m0[s], m1 = tab.m1[s];

        unsigned i0 = 0;
        #pragma unroll
        for (int bIdx = 0; bIdx < 8; bIdx++)
            if ((p >> bIdx) & 1) i0 ^= tab.L[s][bIdx];

        const unsigned i10 = i0 ^ m0;
        const unsigned i01 = i0 ^ m1;
        const unsigned i11 = i10 ^ m1;

        float r00 = sre[i0],  q00 = sim[i0];
        float r10 = sre[i10], q10 = sim[i10];
        float r01 = sre[i01], q01 = sim[i01];
        float r11 = sre[i11], q11 = sim[i11];

        {
            const float Am = Ug[2 * s][0], Bm = Ug[2 * s][1];
            const float Cm = Ug[2 * s][2], Dm = Ug[2 * s][3];
            float nr0 = Am * r00 + Bm * q00 - Cm * r10 + Dm * q10;
            float nq0 = Am * q00 - Bm * r00 - Cm * q10 - Dm * r10;
            float nr1 = Cm * r00 + Dm * q00 + Am * r10 - Bm * q10;
            float nq1 = Cm * q00 - Dm * r00 + Am * q10 + Bm * r10;
            r00 = nr0; q00 = nq0; r10 = nr1; q10 = nq1;
            nr0 = Am * r01 + Bm * q01 - Cm * r11 + Dm * q11;
            nq0 = Am * q01 - Bm * r01 - Cm * q11 - Dm * r11;
            nr1 = Cm * r01 + Dm * q01 + Am * r11 - Bm * q11;
            nq1 = Cm * q01 - Dm * r01 + Am * q11 + Bm * r11;
            r01 = nr0; q01 = nq0; r11 = nr1; q11 = nq1;
        }
        {
            const float Am = Ug[2 * s + 1][0], Bm = Ug[2 * s + 1][1];
            const float Cm = Ug[2 * s + 1][2], Dm = Ug[2 * s + 1][3];
            float nr0 = Am * r00 + Bm * q00 - Cm * r01 + Dm * q01;
            float nq0 = Am * q00 - Bm * r00 - Cm * q01 - Dm * r01;
            float nr1 = Cm * r00 + Dm * q00 + Am * r01 - Bm * q01;
            float nq1 = Cm * q00 - Dm * r00 + Am * q01 + Bm * r01;
            r00 = nr0; q00 = nq0; r01 = nr1; q01 = nq1;
            nr0 = Am * r10 + Bm * q10 - Cm * r11 + Dm * q11;
            nq0 = Am * q10 - Bm * r10 - Cm * q11 - Dm * r11;
            nr1 = Cm * r10 + Dm * q10 + Am * r11 - Bm * q11;
            nq1 = Cm * q10 - Dm * r10 + Am * q11 + Bm * r11;
            r10 = nr0; q10 = nq0; r11 = nr1; q11 = nq1;
        }

        sre[i0]  = r00; sim[i0]  = q00;
        sre[i10] = r10; sim[i10] = q10;
        sre[i01] = r01; sim[i01] = q01;
        sre[i11] = r11; sim[i11] = q11;
        __syncthreads();
    }

    size_t base = (size_t)row * 2048;
    #pragma unroll
    for (int j = 0; j < 4; j++) {
        int b = tid + j * 256;
        unsigned phys = 0;
        #pragma unroll
        for (int k2 = 0; k2 < 10; k2++)
            if ((b >> k2) & 1) phys ^= tab.fcol[k2];
        float pre = sre[phys], pim = sim[phys];
        float pp = pre * pre + pim * pim;
        __nv_bfloat16 hi = __float2bfloat16(pp);
        __nv_bfloat16 lo = __float2bfloat16(pp - __bfloat162float(hi));
        out[base + b] = hi;
        out[base + 1024 + b] = lo;
    }
}

// ---------------------------------------------------------------------------
// Final: y = |x| ; y /= rowsum(y)
// ---------------------------------------------------------------------------
__global__ __launch_bounds__(256) void abs_norm_kernel(
    const float* __restrict__ x, float* __restrict__ out)
{
    __shared__ float red[8];
    const int row = blockIdx.x;
    const int tid = threadIdx.x;

    float v[4];
    float ss = 0.0f;
    #pragma unroll
    for (int j = 0; j < 4; j++) {
        int i = tid + j * 256;
        v[j] = (i < 1000) ? fabsf(x[(size_t)row * 1024 + i]) : 0.0f;
        ss += v[j];
    }
    #pragma unroll
    for (int o = 16; o > 0; o >>= 1)
        ss += __shfl_xor_sync(0xFFFFFFFFu, ss, o);
    if ((tid & 31) == 0) red[tid >> 5] = ss;
    __syncthreads();
    float tot = 0.0f;
    #pragma unroll
    for (int j = 0; j < 8; j++) tot += red[j];
    float inv = 1.0f / tot;
    #pragma unroll
    for (int j = 0; j < 4; j++) {
        int i = tid + j * 256;
        if (i < 1000)
            out[(size_t)row * 1000 + i] = v[j] * inv;
    }
}

// ---------------------------------------------------------------------------
// Host: circuit schedule.
// ---------------------------------------------------------------------------
static int ctz10(unsigned x) { int i = 0; while (!((x >> i) & 1)) i++; return i; }

static CircTab make_circ_tab()
{
    unsigned pc[10], pr[10];
    unsigned gm[30], gr[30];
    for (int j = 0; j < 10; j++) { pc[j] = 1u << j; pr[j] = 1u << j; }
    for (int l = 0; l < 3; l++) {
        for (int q = 0; q < 10; q++) {
            int g = l * 10 + q, b = 9 - q;
            gm[g] = pc[b];
            gr[g] = pr[b];
        }
        int rr = l % 9 + 1;
        for (int q = 0; q < 10; q++) {
            int c = 9 - q;
            int tt = 9 - ((q + rr) % 10);
            pc[c] ^= pc[tt];
            pr[tt] ^= pr[c];
        }
    }
    CircTab t;
    for (int j = 0; j < 10; j++) t.fcol[j] = (unsigned short)pc[j];
    for (int s = 0; s < 15; s++) {
        unsigned r0 = gr[2 * s], r1 = gr[2 * s + 1];
        t.m0[s] = (unsigned short)gm[2 * s];
        t.m1[s] = (unsigned short)gm[2 * s + 1];
        t.r0[s] = (unsigned short)r0;
        t.r1[s] = (unsigned short)r1;
        unsigned a = r0, b = r1;
        int p0 = ctz10(a);
        if ((b >> p0) & 1) b ^= a;
        int p1 = ctz10(b);
        if ((a >> p1) & 1) a ^= b;
        int idx = 0;
        for (int bit = 0; bit < 10; bit++) {
            if (bit == p0 || bit == p1) continue;
            unsigned vv = 1u << bit;
            if (__builtin_popcount(vv & a) & 1) vv ^= 1u << p0;
            if (__builtin_popcount(vv & b) & 1) vv ^= 1u << p1;
            t.L[s][idx++] = (unsigned short)vv;
        }
    }
    return t;
}

// ---------------------------------------------------------------------------
// Launch. Weight-prep chain runs on a forked side stream (captured via
// event fork/join) so it overlaps gemm0 + circuitEnc in the graph.
// Stream/events created once on the first (non-captured) correctness call.
// ---------------------------------------------------------------------------
extern "C" void kernel_launch(void* const* d_in, const int* in_sizes, int n_in,
                              void* d_out, int out_size)
{
    const float* inputs = (const float*)d_in[0];
    const float* wEnc   = (const float*)d_in[1];
    const float* wDec   = (const float*)d_in[2];
    const float* W0     = (const float*)d_in[3];
    const float* b0     = (const float*)d_in[4];
    const float* W1     = (const float*)d_in[5];
    const float* b1     = (const float*)d_in[6];
    const float* W2     = (const float*)d_in[7];
    const float* b2     = (const float*)d_in[8];
    const float* W3     = (const float*)d_in[9];
    const float* b3     = (const float*)d_in[10];
    float* outp = (float*)d_out;

    float *bufA = nullptr, *bufB = nullptr, *bias3 = nullptr, *biasC = nullptr,
          *wcPart = nullptr;
    __nv_bfloat16 *actx2 = nullptr, *w0x = nullptr, *w1e = nullptr,
                  *w2x = nullptr, *w3x = nullptr, *wcx = nullptr;
    cudaGetSymbolAddress((void**)&bufA, g_bufA);
    cudaGetSymbolAddress((void**)&bufB, g_bufB);
    cudaGetSymbolAddress((void**)&bias3, g_bias3);
    cudaGetSymbolAddress((void**)&biasC, g_biasC);
    cudaGetSymbolAddress((void**)&wcPart, g_wcPart);
    cudaGetSymbolAddress((void**)&actx2, g_actx2);
    cudaGetSymbolAddress((void**)&w0x, g_w0x);
    cudaGetSymbolAddress((void**)&w1e, g_w1e);
    cudaGetSymbolAddress((void**)&w2x, g_w2x);
    cudaGetSymbolAddress((void**)&w3x, g_w3x);
    cudaGetSymbolAddress((void**)&wcx, g_wcx);

    const CircTab tab = make_circ_tab();

    dim3 blk(256);
    dim3 blkg(128);
    const int GSMEM = NSTAGE * STAGE_BYTES;   // 98304 B dynamic smem

    // One-time resources (created on the uncaptured correctness call)
    static cudaStream_t s2 = nullptr;
    static cudaEvent_t evF = nullptr, evJ = nullptr;
    if (s2 == nullptr) {
        cudaFuncSetAttribute(gemm_mma,
                             cudaFuncAttributeMaxDynamicSharedMemorySize, GSMEM);
        cudaStreamCreateWithFlags(&s2, cudaStreamNonBlocking);
        cudaEventCreateWithFlags(&evF, cudaEventDisableTiming);
        cudaEventCreateWithFlags(&evJ, cudaEventDisableTiming);
    }

    // ---- fork side stream ----
    cudaEventRecord(evF, 0);
    cudaStreamWaitEvent(s2, evF, 0);

    // ---- side stream: entire weight-prep chain (independent of main) ----
    convert_act<<<1024 * 2048 / 256, blk, 0, s2>>>(W1, w1e, 2048, 2048);
    convert_weight<<<dim3(64, 32), blk, 0, s2>>>(W2, w2x, 2048, 1024, 2048, 1024);
    gemm_mma<<<dim3(8, 8, 4), blkg, GSMEM, s2>>>(1536, 2048, 4096, 1024, 2,
                                                 w1e, w2x, biasC, wcPart);
    reduce_convert_weight<<<dim3(32, 32), blk, 0, s2>>>(wcPart, wcx);
    bias_compose<<<4, blk, 0, s2>>>(b1, W2, b2, biasC);
    convert_weight<<<dim3(32, 32), blk, 0, s2>>>(W3, w3x, 1024, 1000, 1024, 1024);
    pad_bias<<<4, blk, 0, s2>>>(b3, bias3, 1000);
    cudaEventRecord(evJ, s2);

    // ---- main stream ----
    convert_weight<<<dim3(32, 32), blk>>>(W0, w0x, 1000, 1024, 1024, 1024);
    convert_act<<<4096 * 1024 / 256, blk>>>(inputs, actx2, 1000, 1024);
    // x = inputs @ W0 + b0
    gemm_mma<<<dim3(8, 32), blkg, GSMEM>>>(3072, 1024, 2048, 1024, 0,
                                           actx2, w0x, b0, bufA);
    // x = circuit(x, wEnc) -> ext bf16
    circuit_kernel<<<4096, blk>>>(bufA, wEnc, tab, actx2);

    // ---- join: Wc / w3x / biases ready ----
    cudaStreamWaitEvent(0, evJ, 0);

    // x = x @ Wc + bc
    gemm_mma<<<dim3(8, 32), blkg, GSMEM>>>(3072, 1024, 2048, 1024, 0,
                                           actx2, wcx, biasC, bufA);
    // x = circuit(x, wDec) -> ext bf16
    circuit_kernel<<<4096, blk>>>(bufA, wDec, tab, actx2);
    // x = x @ W3 + b3
    gemm_mma<<<dim3(8, 32), blkg, GSMEM>>>(3072, 1024, 2048, 1024, 0,
                                           actx2, w3x, bias3, bufB);
    // out = |x| / rowsum(|x|)
    abs_norm_kernel<<<4096, blk>>>(bufB, outp);
}